// round 1
// baseline (speedup 1.0000x reference)
#include <cuda_runtime.h>

// ============================================================================
// CSNN: 5 conv + IF layers, 3 FC + IF layers, T=8, B=32, firing-rate output.
// Layout convention everywhere: [T][B][C][H][W] row-major (T*B merged = 256).
// ============================================================================

#define TSTEPS 8

// ---------------- static scratch (no cudaMalloc allowed) -------------------
__device__ float g_z1 [32*128*26*26];          // conv1 out (single timestep)
__device__ float g_s1 [8*32*128*26*26];        // spikes layer1
__device__ float g_z2 [8*32*128*13*13];
__device__ float g_s2 [8*32*128*13*13];
__device__ float g_z3 [8*32*192*13*13];
__device__ float g_s3 [8*32*192*13*13];
__device__ float g_z4 [8*32*128*13*13];
__device__ float g_s4 [8*32*128*13*13];
__device__ float g_z5 [8*32*128*6*6];
__device__ float g_s5 [8*32*128*6*6];
__device__ float g_zf1[8*32*2048];
__device__ float g_sf1[8*32*2048];
__device__ float g_zf2[8*32*512];
__device__ float g_sf2[8*32*512];
__device__ float g_zf3[8*32*10];

// ---------------------------------------------------------------------------
// conv1: 1 input channel, computed once (input is time-invariant).
// out[n, oc, oy, ox], n<32, oc<128, 26x26, k=5, s=1, pad=1
// ---------------------------------------------------------------------------
__global__ void conv1_kernel(const float* __restrict__ x,
                             const float* __restrict__ w,
                             const float* __restrict__ b,
                             float* __restrict__ out)
{
    int idx = blockIdx.x * blockDim.x + threadIdx.x;
    if (idx >= 32*128*676) return;
    int pos = idx % 676;
    int oc  = (idx / 676) % 128;
    int n   = idx / (676*128);
    int oy = pos / 26, ox = pos % 26;
    float a = b[oc];
    #pragma unroll
    for (int ky = 0; ky < 5; ky++) {
        int iy = oy + ky - 1;
        if (iy < 0 || iy >= 28) continue;
        #pragma unroll
        for (int kx = 0; kx < 5; kx++) {
            int ix = ox + kx - 1;
            if (ix < 0 || ix >= 28) continue;
            a = fmaf(__ldg(&x[(n*28 + iy)*28 + ix]),
                     __ldg(&w[(oc*5 + ky)*5 + kx]), a);
        }
    }
    out[idx] = a;
}

// ---------------------------------------------------------------------------
// IF neuron scan: v += z; s = (v >= vth); v *= (1-s).  Sequential over T=8,
// parallel over elements. CONST_IN: same pre-activation every step (layer 1).
// MEAN_OUT: emit firing rate instead of spike train (final layer).
// ---------------------------------------------------------------------------
template <bool CONST_IN, bool MEAN_OUT>
__global__ void if_kernel(const float* __restrict__ z, float* __restrict__ s,
                          int E, float vth)
{
    int e = blockIdx.x * blockDim.x + threadIdx.x;
    if (e >= E) return;
    float zc = CONST_IN ? z[e] : 0.f;
    float v = 0.f, m = 0.f;
    #pragma unroll
    for (int t = 0; t < TSTEPS; t++) {
        float xv = CONST_IN ? zc : z[t*E + e];
        v += xv;
        float sp = (v >= vth) ? 1.f : 0.f;
        v -= v * sp;                        // hard reset to 0
        if (MEAN_OUT) m += sp;
        else          s[t*E + e] = sp;
    }
    if (MEAN_OUT) s[e] = m * (1.f / TSTEPS);
}

// ---------------------------------------------------------------------------
// Generic smem-tiled direct convolution over spike inputs.
// Block = (image group of IPB, TC output channels, full OHxOW plane).
// Loops input channels in chunks of CC; skips chunk compute when the loaded
// input tile is all-zero (SNN sparsity).
// Weights padded to KWPAD (mult of 4) in smem -> float4 broadcast loads.
// ---------------------------------------------------------------------------
template <int CIN, int COUT, int IH, int IW, int OH, int OW,
          int KH, int KW, int S, int PAD, int TC, int IPB, int CC, int NT>
__global__ __launch_bounds__(NT) void conv_sp(
    const float* __restrict__ in, const float* __restrict__ wgt,
    const float* __restrict__ bias, float* __restrict__ out, int Nimg)
{
    constexpr int P    = OH * OW;
    constexpr int PIH  = (OH - 1) * S + KH;
    constexpr int PIW  = (OW - 1) * S + KW;
    constexpr int KK   = KH * KW;
    constexpr int KWPAD = (KK + 3) & ~3;

    __shared__ float s_in[IPB][CC][PIH * PIW];
    __shared__ __align__(16) float s_w[CC][TC][KWPAD];

    const int tid     = threadIdx.x;
    const int oc0     = blockIdx.y * TC;
    const int ig0     = blockIdx.z * IPB;
    const int img_sub = tid / P;
    const int pos     = tid - img_sub * P;
    const int oy      = pos / OW;
    const int ox      = pos - oy * OW;
    const bool active = (img_sub < IPB) && (ig0 + img_sub < Nimg);

    float acc[TC];
    #pragma unroll
    for (int i = 0; i < TC; i++) acc[i] = 0.f;

    for (int c0 = 0; c0 < CIN; c0 += CC) {
        // ---- load input tile (zero padded), track nonzero flag ----
        int flag = 0;
        constexpr int LOAD = IPB * CC * PIH * PIW;
        #pragma unroll 1
        for (int i = tid; i < LOAD; i += NT) {
            int im  = i / (CC * PIH * PIW);
            int rem = i - im * (CC * PIH * PIW);
            int cc  = rem / (PIH * PIW);
            int pp  = rem - cc * (PIH * PIW);
            int py  = pp / PIW;
            int px  = pp - py * PIW;
            int iy  = py - PAD, ix = px - PAD;
            int n   = ig0 + im;
            float v = 0.f;
            if (n < Nimg && iy >= 0 && iy < IH && ix >= 0 && ix < IW)
                v = in[((n * CIN + (c0 + cc)) * IH + iy) * IW + ix];
            s_in[im][cc][pp] = v;
            flag |= (v != 0.f);
        }
        int nz = __syncthreads_or(flag);        // acts as the barrier
        if (nz) {
            // ---- load weights for this (oc tile, cin chunk) ----
            constexpr int WLOAD = CC * TC * KK;
            #pragma unroll 1
            for (int i = tid; i < WLOAD; i += NT) {
                int cc  = i / (TC * KK);
                int rem = i - cc * (TC * KK);
                int oc  = rem / KK;
                int k   = rem - oc * KK;
                s_w[cc][oc][k] = wgt[((oc0 + oc) * CIN + (c0 + cc)) * KK + k];
            }
            __syncthreads();
            if (active) {
                #pragma unroll
                for (int cc = 0; cc < CC; cc++) {
                    float xin[KK];
                    #pragma unroll
                    for (int ky = 0; ky < KH; ky++)
                        #pragma unroll
                        for (int kx = 0; kx < KW; kx++)
                            xin[ky*KW + kx] =
                                s_in[img_sub][cc][(oy*S + ky)*PIW + ox*S + kx];
                    #pragma unroll
                    for (int oc = 0; oc < TC; oc++) {
                        float w[KWPAD];
                        #pragma unroll
                        for (int q = 0; q < KWPAD/4; q++) {
                            float4 v4 = *reinterpret_cast<const float4*>(&s_w[cc][oc][q*4]);
                            w[q*4+0] = v4.x; w[q*4+1] = v4.y;
                            w[q*4+2] = v4.z; w[q*4+3] = v4.w;
                        }
                        float a = acc[oc];
                        #pragma unroll
                        for (int k = 0; k < KK; k++)
                            a = fmaf(xin[k], w[k], a);
                        acc[oc] = a;
                    }
                }
            }
            __syncthreads();
        }
    }
    if (active) {
        int n = ig0 + img_sub;
        #pragma unroll
        for (int oc = 0; oc < TC; oc++)
            out[(n * COUT + oc0 + oc) * P + pos] = acc[oc] + bias[oc0 + oc];
    }
}

// ---------------------------------------------------------------------------
// SGEMM  C[M,N] = A[M,K] * B[N,K]^T   (A = spikes, B = fc weight, row-major)
// 64x64x16 tiles, 256 threads, 4x4 micro-tile. Skips K-chunk when the A tile
// is all zero (and then also skips loading the B tile).
// ---------------------------------------------------------------------------
__global__ __launch_bounds__(256) void gemm_nt(
    const float* __restrict__ A, const float* __restrict__ B,
    float* __restrict__ C, int M, int N, int K)
{
    __shared__ float As[16][64];
    __shared__ float Bs[16][64];
    const int tid = threadIdx.x;
    const int tm = tid >> 4, tn = tid & 15;
    const int m0 = blockIdx.y * 64, n0 = blockIdx.x * 64;
    const int r = tid >> 2, q = (tid & 3) << 2;

    float c[4][4];
    #pragma unroll
    for (int i = 0; i < 4; i++)
        #pragma unroll
        for (int j = 0; j < 4; j++) c[i][j] = 0.f;

    for (int k0 = 0; k0 < K; k0 += 16) {
        float4 av = *reinterpret_cast<const float4*>(&A[(m0 + r) * K + k0 + q]);
        As[q+0][r] = av.x; As[q+1][r] = av.y; As[q+2][r] = av.z; As[q+3][r] = av.w;
        int f = (av.x != 0.f) | (av.y != 0.f) | (av.z != 0.f) | (av.w != 0.f);
        if (__syncthreads_or(f)) {
            float4 bv = *reinterpret_cast<const float4*>(&B[(n0 + r) * K + k0 + q]);
            Bs[q+0][r] = bv.x; Bs[q+1][r] = bv.y; Bs[q+2][r] = bv.z; Bs[q+3][r] = bv.w;
            __syncthreads();
            #pragma unroll
            for (int kk = 0; kk < 16; kk++) {
                float4 a = *reinterpret_cast<const float4*>(&As[kk][tm*4]);
                float4 b = *reinterpret_cast<const float4*>(&Bs[kk][tn*4]);
                c[0][0] = fmaf(a.x, b.x, c[0][0]); c[0][1] = fmaf(a.x, b.y, c[0][1]);
                c[0][2] = fmaf(a.x, b.z, c[0][2]); c[0][3] = fmaf(a.x, b.w, c[0][3]);
                c[1][0] = fmaf(a.y, b.x, c[1][0]); c[1][1] = fmaf(a.y, b.y, c[1][1]);
                c[1][2] = fmaf(a.y, b.z, c[1][2]); c[1][3] = fmaf(a.y, b.w, c[1][3]);
                c[2][0] = fmaf(a.z, b.x, c[2][0]); c[2][1] = fmaf(a.z, b.y, c[2][1]);
                c[2][2] = fmaf(a.z, b.z, c[2][2]); c[2][3] = fmaf(a.z, b.w, c[2][3]);
                c[3][0] = fmaf(a.w, b.x, c[3][0]); c[3][1] = fmaf(a.w, b.y, c[3][1]);
                c[3][2] = fmaf(a.w, b.z, c[3][2]); c[3][3] = fmaf(a.w, b.w, c[3][3]);
            }
            __syncthreads();
        }
    }
    #pragma unroll
    for (int i = 0; i < 4; i++)
        #pragma unroll
        for (int j = 0; j < 4; j++)
            C[(m0 + tm*4 + i) * N + n0 + tn*4 + j] = c[i][j];
}

// ---------------------------------------------------------------------------
// fc3: tiny (256x10, K=512) — one thread per output element.
// ---------------------------------------------------------------------------
__global__ void fc3_kernel(const float* __restrict__ A,
                           const float* __restrict__ W,
                           float* __restrict__ C)
{
    int idx = blockIdx.x * blockDim.x + threadIdx.x;
    if (idx >= 256 * 10) return;
    int n = idx % 10, m = idx / 10;
    const float* ar = A + m * 512;
    const float* wr = W + n * 512;
    float a = 0.f;
    #pragma unroll 4
    for (int k = 0; k < 512; k += 4) {
        float4 av = *reinterpret_cast<const float4*>(ar + k);
        float4 wv = *reinterpret_cast<const float4*>(wr + k);
        a = fmaf(av.x, wv.x, a); a = fmaf(av.y, wv.y, a);
        a = fmaf(av.z, wv.z, a); a = fmaf(av.w, wv.w, a);
    }
    C[idx] = a;
}

// ---------------------------------------------------------------------------
extern "C" void kernel_launch(void* const* d_in, const int* in_sizes, int n_in,
                              void* d_out, int out_size)
{
    (void)in_sizes; (void)n_in; (void)out_size;
    const float* x    = (const float*)d_in[0];
    const float* w1   = (const float*)d_in[1];
    const float* b1   = (const float*)d_in[2];
    const float* w2   = (const float*)d_in[3];
    const float* b2   = (const float*)d_in[4];
    const float* w3   = (const float*)d_in[5];
    const float* b3   = (const float*)d_in[6];
    const float* w4   = (const float*)d_in[7];
    const float* b4   = (const float*)d_in[8];
    const float* w5   = (const float*)d_in[9];
    const float* b5   = (const float*)d_in[10];
    const float* fc1w = (const float*)d_in[11];
    const float* fc2w = (const float*)d_in[12];
    const float* fc3w = (const float*)d_in[13];
    float* out = (float*)d_out;

    float *z1,*s1,*z2,*s2,*z3,*s3,*z4,*s4,*z5,*s5,*zf1,*sf1,*zf2,*sf2,*zf3;
    cudaGetSymbolAddress((void**)&z1,  g_z1);
    cudaGetSymbolAddress((void**)&s1,  g_s1);
    cudaGetSymbolAddress((void**)&z2,  g_z2);
    cudaGetSymbolAddress((void**)&s2,  g_s2);
    cudaGetSymbolAddress((void**)&z3,  g_z3);
    cudaGetSymbolAddress((void**)&s3,  g_s3);
    cudaGetSymbolAddress((void**)&z4,  g_z4);
    cudaGetSymbolAddress((void**)&s4,  g_s4);
    cudaGetSymbolAddress((void**)&z5,  g_z5);
    cudaGetSymbolAddress((void**)&s5,  g_s5);
    cudaGetSymbolAddress((void**)&zf1, g_zf1);
    cudaGetSymbolAddress((void**)&sf1, g_sf1);
    cudaGetSymbolAddress((void**)&zf2, g_zf2);
    cudaGetSymbolAddress((void**)&sf2, g_sf2);
    cudaGetSymbolAddress((void**)&zf3, g_zf3);

    const int TB = 8 * 32;   // merged T*B image count

    // L1: conv1 once (time-invariant input) + IF scan with constant input
    const int E1 = 32*128*26*26;
    conv1_kernel<<<(E1 + 255)/256, 256>>>(x, w1, b1, z1);
    if_kernel<true, false><<<(E1 + 255)/256, 256>>>(z1, s1, E1, 13515.f);

    // L2: conv 128->128 4x4 s2 p1 on 26x26 -> 13x13
    conv_sp<128,128,26,26,13,13,4,4,2,1, 16,1,4,192>
        <<<dim3(1, 128/16, TB), 192>>>(s1, w2, b2, z2, TB);
    const int E2 = 32*128*13*13;
    if_kernel<false,false><<<(E2 + 255)/256, 256>>>(z2, s2, E2, 71.f);

    // L3: conv 128->192 3x3 s1 p1 on 13x13
    conv_sp<128,192,13,13,13,13,3,3,1,1, 16,1,8,192>
        <<<dim3(1, 192/16, TB), 192>>>(s2, w3, b3, z3, TB);
    const int E3 = 32*192*13*13;
    if_kernel<false,false><<<(E3 + 255)/256, 256>>>(z3, s3, E3, 93.f);

    // L4: conv 192->128 3x3 s1 p1 on 13x13
    conv_sp<192,128,13,13,13,13,3,3,1,1, 16,1,8,192>
        <<<dim3(1, 128/16, TB), 192>>>(s3, w4, b4, z4, TB);
    const int E4 = 32*128*13*13;
    if_kernel<false,false><<<(E4 + 255)/256, 256>>>(z4, s4, E4, 144.f);

    // L5: conv 128->128 3x3 s2 p0 on 13x13 -> 6x6 (7 images per block)
    conv_sp<128,128,13,13,6,6,3,3,2,0, 16,7,4,256>
        <<<dim3(1, 128/16, (TB + 6)/7), 256>>>(s4, w5, b5, z5, TB);
    const int E5 = 32*128*6*6;
    if_kernel<false,false><<<(E5 + 255)/256, 256>>>(z5, s5, E5, 79.f);

    // FC1: [256,4608] x [2048,4608]^T
    gemm_nt<<<dim3(2048/64, 256/64), 256>>>(s5, fc1w, zf1, 256, 2048, 4608);
    const int Ef1 = 32*2048;
    if_kernel<false,false><<<(Ef1 + 255)/256, 256>>>(zf1, sf1, Ef1, 2475.f);

    // FC2: [256,2048] x [512,2048]^T
    gemm_nt<<<dim3(512/64, 256/64), 256>>>(sf1, fc2w, zf2, 256, 512, 2048);
    const int Ef2 = 32*512;
    if_kernel<false,false><<<(Ef2 + 255)/256, 256>>>(zf2, sf2, Ef2, 1357.f);

    // FC3: [256,512] x [10,512]^T, then IF + mean over T -> d_out [32,10]
    fc3_kernel<<<(2560 + 255)/256, 256>>>(sf2, fc3w, zf3);
    if_kernel<false, true><<<(320 + 255)/256, 256>>>(zf3, out, 320, 388.f);
}

// round 2
// speedup vs baseline: 5.3133x; 5.3133x over previous
#include <cuda_runtime.h>

// ============================================================================
// CSNN (T=8, B=32): 5 conv+IF, 3 FC+IF, firing-rate output [32,10].
// Spiking sparsity exploited with producer-written nonzero flags so consumers
// skip loads of all-zero channel groups. Spikes stored as uint8. Conv+IF fused
// per layer (IF membrane state in registers across the t-loop).
// Layout: [T][B][C][H][W] row-major, n = t*32 + b.
// ============================================================================

#define TSTEPS 8
#define BATCH  32

typedef unsigned char u8;
typedef unsigned int  u32;

// ---------------- static scratch (no cudaMalloc allowed) -------------------
__device__ u8    g_s1 [8*32*128*26*26];
__device__ u8    g_s2 [8*32*128*13*13];
__device__ u8    g_s3 [8*32*192*13*13];
__device__ u8    g_s4 [8*32*128*13*13];
__device__ u8    g_s5 [8*32*128*6*6];
__device__ float g_zf1[8*32*2048];
__device__ u8    g_sf1[8*32*2048];
__device__ float g_zf2[8*32*512];
__device__ u8    g_sf2[8*32*512];
__device__ float g_zf3[8*32*10];

// nonzero flags: one u32 per (n, 16-channel group)
// f1: 256*8 @0   f2: 256*8 @2048   f3: 256*12 @4096   f4: 256*8 @7168
// f5: 256*8 @9216 (written, unused)            total 11264
#define NFLAGS 11264
__device__ u32 g_flags[NFLAGS];

__global__ void zero_flags(u32* f)
{
    int i = blockIdx.x * blockDim.x + threadIdx.x;
    if (i < NFLAGS) f[i] = 0u;
}

// ---------------------------------------------------------------------------
// Layer 1 fused: conv(1ch,5x5,s1,p1) computed ONCE (input time-invariant),
// then IF scan over T with constant drive. Writes u8 spikes + flags.
// ---------------------------------------------------------------------------
__global__ void conv1_if(const float* __restrict__ x,
                         const float* __restrict__ w,
                         const float* __restrict__ b,
                         u8* __restrict__ s1, u32* __restrict__ f1, float vth)
{
    const int E = 32*128*676;
    int idx = blockIdx.x * blockDim.x + threadIdx.x;
    if (idx >= E) return;
    int pos = idx % 676;
    int oc  = (idx / 676) % 128;
    int n   = idx / (676*128);
    int oy = pos / 26, ox = pos % 26;

    float a = b[oc];
    #pragma unroll
    for (int ky = 0; ky < 5; ky++) {
        int iy = oy + ky - 1;
        if (iy < 0 || iy >= 28) continue;
        #pragma unroll
        for (int kx = 0; kx < 5; kx++) {
            int ix = ox + kx - 1;
            if (ix < 0 || ix >= 28) continue;
            a = fmaf(__ldg(&x[(n*28 + iy)*28 + ix]),
                     __ldg(&w[(oc*5 + ky)*5 + kx]), a);
        }
    }

    float v = 0.f;
    #pragma unroll
    for (int t = 0; t < TSTEPS; t++) {
        v += a;
        float sp = (v >= vth) ? 1.f : 0.f;
        v -= v * sp;
        s1[t*E + idx] = (u8)sp;
        if (sp != 0.f)
            atomicOr(&f1[(t*BATCH + n)*8 + (oc >> 4)], 1u);
    }
}

// ---------------------------------------------------------------------------
// Fused conv + IF for layers 2..5. Block = (IPB images, TC out-channels, full
// output plane). Loops t inside; membrane potential kept in registers.
// Consumer-side flag check skips load+compute of zero input chunks (uniform
// branch). Input spikes u8 -> float at smem fill.
// ---------------------------------------------------------------------------
template <int CIN, int COUT, int IH, int IW, int OH, int OW,
          int KH, int KW, int S, int PAD, int TC, int IPB, int CC, int NT>
__global__ __launch_bounds__(NT) void conv_if(
    const u8* __restrict__ in, const float* __restrict__ wgt,
    const float* __restrict__ bias, u8* __restrict__ sout,
    const u32* __restrict__ fin, u32* __restrict__ fout, float vth)
{
    constexpr int P     = OH * OW;
    constexpr int PIH   = (OH - 1) * S + KH;
    constexpr int PIW   = (OW - 1) * S + KW;
    constexpr int KK    = KH * KW;
    constexpr int KWPAD = (KK + 3) & ~3;
    constexpr int GIN   = CIN / 16;
    constexpr int GOUT  = COUT / 16;

    __shared__ float s_in[IPB][CC][PIH * PIW];
    __shared__ __align__(16) float s_w[CC][TC][KWPAD];
    __shared__ u32 s_f[IPB];

    const int tid     = threadIdx.x;
    const int oc0     = blockIdx.y * TC;
    const int b0      = blockIdx.z * IPB;
    const int img_sub = tid / P;
    const int pos     = tid - img_sub * P;
    const int oy      = pos / OW;
    const int ox      = pos - oy * OW;
    const bool active = (img_sub < IPB) && (b0 + img_sub < BATCH);

    float bi[TC];
    #pragma unroll
    for (int i = 0; i < TC; i++) bi[i] = bias[oc0 + i];

    float v[TC];
    #pragma unroll
    for (int i = 0; i < TC; i++) v[i] = 0.f;

    for (int t = 0; t < TSTEPS; t++) {
        const int n_base = t * BATCH + b0;
        if (tid < IPB) s_f[tid] = 0u;
        __syncthreads();

        float acc[TC];
        #pragma unroll
        for (int i = 0; i < TC; i++) acc[i] = 0.f;

        for (int c0 = 0; c0 < CIN; c0 += CC) {
            // uniform flag check (all threads read identical global words)
            u32 nz = 0;
            #pragma unroll
            for (int im = 0; im < IPB; im++)
                if (b0 + im < BATCH)
                    nz |= fin[(n_base + im) * GIN + (c0 >> 4)];
            if (!nz) continue;

            // ---- load input tile (u8 -> float, zero padded) ----
            constexpr int LOAD = IPB * CC * PIH * PIW;
            #pragma unroll 1
            for (int i = tid; i < LOAD; i += NT) {
                int im  = i / (CC * PIH * PIW);
                int rem = i - im * (CC * PIH * PIW);
                int cc  = rem / (PIH * PIW);
                int pp  = rem - cc * (PIH * PIW);
                int py  = pp / PIW;
                int px  = pp - py * PIW;
                int iy  = py - PAD, ix = px - PAD;
                int bim = b0 + im;
                float val = 0.f;
                if (bim < BATCH && iy >= 0 && iy < IH && ix >= 0 && ix < IW)
                    val = (float)in[(((t*BATCH + bim) * CIN + (c0 + cc)) * IH + iy) * IW + ix];
                s_in[im][cc][pp] = val;
            }
            // ---- load weights ----
            constexpr int WLOAD = CC * TC * KK;
            #pragma unroll 1
            for (int i = tid; i < WLOAD; i += NT) {
                int cc  = i / (TC * KK);
                int rem = i - cc * (TC * KK);
                int oc  = rem / KK;
                int k   = rem - oc * KK;
                s_w[cc][oc][k] = wgt[((oc0 + oc) * CIN + (c0 + cc)) * KK + k];
            }
            __syncthreads();
            if (active) {
                #pragma unroll
                for (int cc = 0; cc < CC; cc++) {
                    float xin[KK];
                    #pragma unroll
                    for (int ky = 0; ky < KH; ky++)
                        #pragma unroll
                        for (int kx = 0; kx < KW; kx++)
                            xin[ky*KW + kx] =
                                s_in[img_sub][cc][(oy*S + ky)*PIW + ox*S + kx];
                    #pragma unroll
                    for (int oc = 0; oc < TC; oc++) {
                        float w[KWPAD];
                        #pragma unroll
                        for (int q = 0; q < KWPAD/4; q++) {
                            float4 v4 = *reinterpret_cast<const float4*>(&s_w[cc][oc][q*4]);
                            w[q*4+0] = v4.x; w[q*4+1] = v4.y;
                            w[q*4+2] = v4.z; w[q*4+3] = v4.w;
                        }
                        float a = acc[oc];
                        #pragma unroll
                        for (int k = 0; k < KK; k++)
                            a = fmaf(xin[k], w[k], a);
                        acc[oc] = a;
                    }
                }
            }
            __syncthreads();
        }

        // ---- IF update + spike store ----
        if (active) {
            int n = n_base + img_sub;
            u32 any = 0;
            #pragma unroll
            for (int oc = 0; oc < TC; oc++) {
                v[oc] += acc[oc] + bi[oc];
                float sp = (v[oc] >= vth) ? 1.f : 0.f;
                v[oc] -= v[oc] * sp;
                sout[(n * COUT + oc0 + oc) * P + pos] = (u8)sp;
                any |= (sp != 0.f);
            }
            if (any) s_f[img_sub] = 1u;   // benign smem race (all write 1)
        }
        __syncthreads();
        if (tid < IPB && b0 + tid < BATCH && s_f[tid])
            fout[(n_base + tid) * GOUT + (oc0 >> 4)] = 1u;
    }
}

// ---------------------------------------------------------------------------
// SGEMM C[M,N] = A[M,K](u8 spikes) * B[N,K]^T (float weights).
// 64x64x16 tiles, 256 threads, 4x4 micro-tile, zero-A-chunk skip.
// ---------------------------------------------------------------------------
__global__ __launch_bounds__(256) void gemm_nt(
    const u8* __restrict__ A, const float* __restrict__ B,
    float* __restrict__ C, int M, int N, int K)
{
    __shared__ float As[16][64];
    __shared__ float Bs[16][64];
    const int tid = threadIdx.x;
    const int tm = tid >> 4, tn = tid & 15;
    const int m0 = blockIdx.y * 64, n0 = blockIdx.x * 64;
    const int r = tid >> 2, q = (tid & 3) << 2;

    float c[4][4];
    #pragma unroll
    for (int i = 0; i < 4; i++)
        #pragma unroll
        for (int j = 0; j < 4; j++) c[i][j] = 0.f;

    for (int k0 = 0; k0 < K; k0 += 16) {
        uchar4 av = *reinterpret_cast<const uchar4*>(&A[(m0 + r) * K + k0 + q]);
        As[q+0][r] = (float)av.x; As[q+1][r] = (float)av.y;
        As[q+2][r] = (float)av.z; As[q+3][r] = (float)av.w;
        int f = av.x | av.y | av.z | av.w;
        if (__syncthreads_or(f)) {
            float4 bv = *reinterpret_cast<const float4*>(&B[(n0 + r) * K + k0 + q]);
            Bs[q+0][r] = bv.x; Bs[q+1][r] = bv.y; Bs[q+2][r] = bv.z; Bs[q+3][r] = bv.w;
            __syncthreads();
            #pragma unroll
            for (int kk = 0; kk < 16; kk++) {
                float4 a = *reinterpret_cast<const float4*>(&As[kk][tm*4]);
                float4 b = *reinterpret_cast<const float4*>(&Bs[kk][tn*4]);
                c[0][0] = fmaf(a.x, b.x, c[0][0]); c[0][1] = fmaf(a.x, b.y, c[0][1]);
                c[0][2] = fmaf(a.x, b.z, c[0][2]); c[0][3] = fmaf(a.x, b.w, c[0][3]);
                c[1][0] = fmaf(a.y, b.x, c[1][0]); c[1][1] = fmaf(a.y, b.y, c[1][1]);
                c[1][2] = fmaf(a.y, b.z, c[1][2]); c[1][3] = fmaf(a.y, b.w, c[1][3]);
                c[2][0] = fmaf(a.z, b.x, c[2][0]); c[2][1] = fmaf(a.z, b.y, c[2][1]);
                c[2][2] = fmaf(a.z, b.z, c[2][2]); c[2][3] = fmaf(a.z, b.w, c[2][3]);
                c[3][0] = fmaf(a.w, b.x, c[3][0]); c[3][1] = fmaf(a.w, b.y, c[3][1]);
                c[3][2] = fmaf(a.w, b.z, c[3][2]); c[3][3] = fmaf(a.w, b.w, c[3][3]);
            }
            __syncthreads();
        }
    }
    #pragma unroll
    for (int i = 0; i < 4; i++)
        #pragma unroll
        for (int j = 0; j < 4; j++)
            C[(m0 + tm*4 + i) * N + n0 + tn*4 + j] = c[i][j];
}

// ---------------------------------------------------------------------------
// IF scan for FC layers (float pre-activation in, OutT spikes out).
// MEAN_OUT: emit firing rate (final layer, float).
// ---------------------------------------------------------------------------
template <bool MEAN_OUT, typename OutT>
__global__ void if_kernel(const float* __restrict__ z, OutT* __restrict__ s,
                          int E, float vth)
{
    int e = blockIdx.x * blockDim.x + threadIdx.x;
    if (e >= E) return;
    float v = 0.f, m = 0.f;
    #pragma unroll
    for (int t = 0; t < TSTEPS; t++) {
        v += z[t*E + e];
        float sp = (v >= vth) ? 1.f : 0.f;
        v -= v * sp;
        if (MEAN_OUT) m += sp;
        else          s[t*E + e] = (OutT)sp;
    }
    if (MEAN_OUT) s[e] = (OutT)(m * (1.f / TSTEPS));
}

// ---------------------------------------------------------------------------
// fc3: tiny (256x10, K=512) — one thread per output element.
// ---------------------------------------------------------------------------
__global__ void fc3_kernel(const u8* __restrict__ A,
                           const float* __restrict__ W,
                           float* __restrict__ C)
{
    int idx = blockIdx.x * blockDim.x + threadIdx.x;
    if (idx >= 256 * 10) return;
    int n = idx % 10, m = idx / 10;
    const u8*    ar = A + m * 512;
    const float* wr = W + n * 512;
    float a = 0.f;
    #pragma unroll 4
    for (int k = 0; k < 512; k += 4) {
        uchar4 av = *reinterpret_cast<const uchar4*>(ar + k);
        float4 wv = *reinterpret_cast<const float4*>(wr + k);
        a = fmaf((float)av.x, wv.x, a); a = fmaf((float)av.y, wv.y, a);
        a = fmaf((float)av.z, wv.z, a); a = fmaf((float)av.w, wv.w, a);
    }
    C[idx] = a;
}

// ---------------------------------------------------------------------------
extern "C" void kernel_launch(void* const* d_in, const int* in_sizes, int n_in,
                              void* d_out, int out_size)
{
    (void)in_sizes; (void)n_in; (void)out_size;
    const float* x    = (const float*)d_in[0];
    const float* w1   = (const float*)d_in[1];
    const float* b1   = (const float*)d_in[2];
    const float* w2   = (const float*)d_in[3];
    const float* b2   = (const float*)d_in[4];
    const float* w3   = (const float*)d_in[5];
    const float* b3   = (const float*)d_in[6];
    const float* w4   = (const float*)d_in[7];
    const float* b4   = (const float*)d_in[8];
    const float* w5   = (const float*)d_in[9];
    const float* b5   = (const float*)d_in[10];
    const float* fc1w = (const float*)d_in[11];
    const float* fc2w = (const float*)d_in[12];
    const float* fc3w = (const float*)d_in[13];
    float* out = (float*)d_out;

    u8 *s1,*s2,*s3,*s4,*s5,*sf1,*sf2;
    float *zf1,*zf2,*zf3;
    u32 *flags;
    cudaGetSymbolAddress((void**)&s1,  g_s1);
    cudaGetSymbolAddress((void**)&s2,  g_s2);
    cudaGetSymbolAddress((void**)&s3,  g_s3);
    cudaGetSymbolAddress((void**)&s4,  g_s4);
    cudaGetSymbolAddress((void**)&s5,  g_s5);
    cudaGetSymbolAddress((void**)&zf1, g_zf1);
    cudaGetSymbolAddress((void**)&sf1, g_sf1);
    cudaGetSymbolAddress((void**)&zf2, g_zf2);
    cudaGetSymbolAddress((void**)&sf2, g_sf2);
    cudaGetSymbolAddress((void**)&zf3, g_zf3);
    cudaGetSymbolAddress((void**)&flags, g_flags);

    u32* f1 = flags + 0;
    u32* f2 = flags + 2048;
    u32* f3 = flags + 4096;
    u32* f4 = flags + 7168;
    u32* f5 = flags + 9216;

    zero_flags<<<(NFLAGS + 255)/256, 256>>>(flags);

    // L1: conv1 once + IF with constant drive
    const int E1 = 32*128*676;
    conv1_if<<<(E1 + 255)/256, 256>>>(x, w1, b1, s1, f1, 13515.f);

    // L2: 128->128, 4x4, s2, p1, 26->13
    conv_if<128,128,26,26,13,13,4,4,2,1, 16,1,4,192>
        <<<dim3(1, 8, 32), 192>>>(s1, w2, b2, s2, f1, f2, 71.f);

    // L3: 128->192, 3x3, s1, p1, 13->13
    conv_if<128,192,13,13,13,13,3,3,1,1, 16,1,8,192>
        <<<dim3(1, 12, 32), 192>>>(s2, w3, b3, s3, f2, f3, 93.f);

    // L4: 192->128, 3x3, s1, p1, 13->13
    conv_if<192,128,13,13,13,13,3,3,1,1, 16,1,8,192>
        <<<dim3(1, 8, 32), 192>>>(s3, w4, b4, s4, f3, f4, 144.f);

    // L5: 128->128, 3x3, s2, p0, 13->6  (7 images per block)
    conv_if<128,128,13,13,6,6,3,3,2,0, 16,7,4,256>
        <<<dim3(1, 8, 5), 256>>>(s4, w5, b5, s5, f4, f5, 79.f);

    // FC1: [256,4608] x [2048,4608]^T  + IF
    gemm_nt<<<dim3(2048/64, 256/64), 256>>>(s5, fc1w, zf1, 256, 2048, 4608);
    if_kernel<false, u8><<<(32*2048 + 255)/256, 256>>>(zf1, sf1, 32*2048, 2475.f);

    // FC2: [256,2048] x [512,2048]^T  + IF
    gemm_nt<<<dim3(512/64, 256/64), 256>>>(sf1, fc2w, zf2, 256, 512, 2048);
    if_kernel<false, u8><<<(32*512 + 255)/256, 256>>>(zf2, sf2, 32*512, 1357.f);

    // FC3 + IF + mean over T -> [32,10]
    fc3_kernel<<<(2560 + 255)/256, 256>>>(sf2, fc3w, zf3);
    if_kernel<true, float><<<(320 + 255)/256, 256>>>(zf3, out, 320, 388.f);
}

// round 3
// speedup vs baseline: 7.8995x; 1.4867x over previous
#include <cuda_runtime.h>

// ============================================================================
// CSNN (T=8, B=32): 5 conv+IF, 3 FC+IF, firing-rate output [32,10].
// Spiking sparsity: producer-written nonzero flags; consumers hoist all flags
// into smem once (parallel) so the zero path has no serialized global latency.
// Spikes stored as uint8. Conv+IF fused per layer (membrane in registers).
// Layout: [T][B][C][H][W] row-major, n = t*32 + b.
// ============================================================================

#define TSTEPS 8
#define BATCH  32

typedef unsigned char u8;
typedef unsigned int  u32;

// ---------------- static scratch (no cudaMalloc allowed) -------------------
__device__ u8    g_s1 [8*32*128*26*26];
__device__ u8    g_s2 [8*32*128*13*13];
__device__ u8    g_s3 [8*32*192*13*13];
__device__ u8    g_s4 [8*32*128*13*13];
__device__ u8    g_s5 [8*32*128*6*6];
__device__ float g_zf1[8*32*2048];
__device__ u8    g_sf1[8*32*2048];
__device__ float g_zf2[8*32*512];
__device__ u8    g_sf2[8*32*512];
__device__ float g_zf3[8*32*10];

// flag memory map (u32 words):
//  f1 @0      (256*8)    per-(n, cin-group16) flags for s1
//  f2 @2048   (256*8)    s2
//  f3 @4096   (256*12)   s3
//  f4 @7168   (256*8)    s4
//  f5 @9216   (256*8)    s5
//  gany5  @11264 (8)     global any-spike per 16-ch group in s5   (FC1 skip)
//  ganyf1 @11272 (128)   global any per 16-feature group in sf1   (FC2 skip)
//  ganyf2 @11400 (32)    global any per 16-feature group in sf2   (unused by fc3, kept)
//  dummy  @11432 (32)    sink for conv layers 2-4 gany writes
#define NFLAGS 11520
__device__ u32 g_flags[NFLAGS];

__global__ void zero_flags(u32* f)
{
    int i = blockIdx.x * blockDim.x + threadIdx.x;
    if (i < NFLAGS) f[i] = 0u;
}

// ---------------------------------------------------------------------------
// Layer 1 fused: conv(1ch,5x5,s1,p1) computed ONCE (input time-invariant),
// then IF scan over T with constant drive. Writes u8 spikes + flags.
// ---------------------------------------------------------------------------
__global__ void conv1_if(const float* __restrict__ x,
                         const float* __restrict__ w,
                         const float* __restrict__ b,
                         u8* __restrict__ s1, u32* __restrict__ f1, float vth)
{
    const int E = 32*128*676;
    int idx = blockIdx.x * blockDim.x + threadIdx.x;
    if (idx >= E) return;
    int pos = idx % 676;
    int oc  = (idx / 676) % 128;
    int n   = idx / (676*128);
    int oy = pos / 26, ox = pos % 26;

    float a = b[oc];
    #pragma unroll
    for (int ky = 0; ky < 5; ky++) {
        int iy = oy + ky - 1;
        if (iy < 0 || iy >= 28) continue;
        #pragma unroll
        for (int kx = 0; kx < 5; kx++) {
            int ix = ox + kx - 1;
            if (ix < 0 || ix >= 28) continue;
            a = fmaf(__ldg(&x[(n*28 + iy)*28 + ix]),
                     __ldg(&w[(oc*5 + ky)*5 + kx]), a);
        }
    }

    float v = 0.f;
    #pragma unroll
    for (int t = 0; t < TSTEPS; t++) {
        v += a;
        float sp = (v >= vth) ? 1.f : 0.f;
        v -= v * sp;
        s1[t*E + idx] = (u8)sp;
        if (sp != 0.f)
            atomicOr(&f1[(t*BATCH + n)*8 + (oc >> 4)], 1u);
    }
}

// ---------------------------------------------------------------------------
// Fused conv + IF for layers 2..5. All input flags hoisted into smem at start
// (one parallel load round) so the zero path is smem-check only.
// ---------------------------------------------------------------------------
template <int CIN, int COUT, int IH, int IW, int OH, int OW,
          int KH, int KW, int S, int PAD, int TC, int IPB, int CC, int NT>
__global__ __launch_bounds__(NT) void conv_if(
    const u8* __restrict__ in, const float* __restrict__ wgt,
    const float* __restrict__ bias, u8* __restrict__ sout,
    const u32* __restrict__ fin, u32* __restrict__ fout,
    u32* __restrict__ gany, float vth)
{
    constexpr int P     = OH * OW;
    constexpr int PIH   = (OH - 1) * S + KH;
    constexpr int PIW   = (OW - 1) * S + KW;
    constexpr int KK    = KH * KW;
    constexpr int KWPAD = (KK + 3) & ~3;
    constexpr int GIN   = CIN / 16;
    constexpr int GOUT  = COUT / 16;

    __shared__ float s_in[IPB][CC][PIH * PIW];
    __shared__ __align__(16) float s_w[CC][TC][KWPAD];
    __shared__ u32 s_f[IPB];
    __shared__ u32 s_fin[TSTEPS][GIN];   // OR across the block's IPB images

    const int tid     = threadIdx.x;
    const int oc0     = blockIdx.y * TC;
    const int b0      = blockIdx.z * IPB;
    const int img_sub = tid / P;
    const int pos     = tid - img_sub * P;
    const int oy      = pos / OW;
    const int ox      = pos - oy * OW;
    const bool active = (img_sub < IPB) && (b0 + img_sub < BATCH);

    // ---- hoist all input flags for all timesteps (parallel, once) ----
    #pragma unroll 1
    for (int i = tid; i < TSTEPS * GIN; i += NT) {
        int tt = i / GIN, gg = i - tt * GIN;
        u32 z = 0;
        #pragma unroll
        for (int im = 0; im < IPB; im++)
            if (b0 + im < BATCH)
                z |= fin[((tt*BATCH) + b0 + im) * GIN + gg];
        s_fin[tt][gg] = z;
    }

    float bi[TC];
    #pragma unroll
    for (int i = 0; i < TC; i++) bi[i] = bias[oc0 + i];

    float v[TC];
    #pragma unroll
    for (int i = 0; i < TC; i++) v[i] = 0.f;

    __syncthreads();

    for (int t = 0; t < TSTEPS; t++) {
        const int n_base = t * BATCH + b0;
        if (tid < IPB) s_f[tid] = 0u;
        __syncthreads();

        float acc[TC];
        #pragma unroll
        for (int i = 0; i < TC; i++) acc[i] = 0.f;

        #pragma unroll 1
        for (int c0 = 0; c0 < CIN; c0 += CC) {
            if (!s_fin[t][c0 >> 4]) continue;    // uniform smem check

            // ---- load input tile (u8 -> float, zero padded) ----
            constexpr int LOAD = IPB * CC * PIH * PIW;
            #pragma unroll 1
            for (int i = tid; i < LOAD; i += NT) {
                int im  = i / (CC * PIH * PIW);
                int rem = i - im * (CC * PIH * PIW);
                int cc  = rem / (PIH * PIW);
                int pp  = rem - cc * (PIH * PIW);
                int py  = pp / PIW;
                int px  = pp - py * PIW;
                int iy  = py - PAD, ix = px - PAD;
                int bim = b0 + im;
                float val = 0.f;
                if (bim < BATCH && iy >= 0 && iy < IH && ix >= 0 && ix < IW)
                    val = (float)in[(((t*BATCH + bim) * CIN + (c0 + cc)) * IH + iy) * IW + ix];
                s_in[im][cc][pp] = val;
            }
            // ---- load weights ----
            constexpr int WLOAD = CC * TC * KK;
            #pragma unroll 1
            for (int i = tid; i < WLOAD; i += NT) {
                int cc  = i / (TC * KK);
                int rem = i - cc * (TC * KK);
                int oc  = rem / KK;
                int k   = rem - oc * KK;
                s_w[cc][oc][k] = wgt[((oc0 + oc) * CIN + (c0 + cc)) * KK + k];
            }
            __syncthreads();
            if (active) {
                #pragma unroll
                for (int cc = 0; cc < CC; cc++) {
                    float xin[KK];
                    #pragma unroll
                    for (int ky = 0; ky < KH; ky++)
                        #pragma unroll
                        for (int kx = 0; kx < KW; kx++)
                            xin[ky*KW + kx] =
                                s_in[img_sub][cc][(oy*S + ky)*PIW + ox*S + kx];
                    #pragma unroll
                    for (int oc = 0; oc < TC; oc++) {
                        float w[KWPAD];
                        #pragma unroll
                        for (int q = 0; q < KWPAD/4; q++) {
                            float4 v4 = *reinterpret_cast<const float4*>(&s_w[cc][oc][q*4]);
                            w[q*4+0] = v4.x; w[q*4+1] = v4.y;
                            w[q*4+2] = v4.z; w[q*4+3] = v4.w;
                        }
                        float a = acc[oc];
                        #pragma unroll
                        for (int k = 0; k < KK; k++)
                            a = fmaf(xin[k], w[k], a);
                        acc[oc] = a;
                    }
                }
            }
            __syncthreads();
        }

        // ---- IF update + spike store ----
        if (active) {
            int n = n_base + img_sub;
            u32 any = 0;
            #pragma unroll
            for (int oc = 0; oc < TC; oc++) {
                v[oc] += acc[oc] + bi[oc];
                float sp = (v[oc] >= vth) ? 1.f : 0.f;
                v[oc] -= v[oc] * sp;
                sout[(n * COUT + oc0 + oc) * P + pos] = (u8)sp;
                any |= (sp != 0.f);
            }
            if (any) s_f[img_sub] = 1u;   // benign smem race (all write 1)
        }
        __syncthreads();
        if (tid < IPB && b0 + tid < BATCH && s_f[tid]) {
            fout[(n_base + tid) * GOUT + (oc0 >> 4)] = 1u;
            gany[oc0 >> 4] = 1u;
        }
    }
}

// ---------------------------------------------------------------------------
// SGEMM C[M,N] = A[M,K](u8 spikes) * B[N,K]^T (float weights).
// 64x64x16 tiles, 256 threads, 4x4 micro-tile.
// Coarse skip: global any-flags per 16-channel group (k -> group via ppc =
// K-elements per channel). Fine skip: per-tile __syncthreads_or fallback.
// ---------------------------------------------------------------------------
__global__ __launch_bounds__(256) void gemm_nt(
    const u8* __restrict__ A, const float* __restrict__ B,
    float* __restrict__ C, int M, int N, int K,
    const u32* __restrict__ gany, int ppc)
{
    __shared__ float As[16][64];
    __shared__ float Bs[16][64];
    __shared__ u32 s_any[128];
    const int tid = threadIdx.x;
    const int tm = tid >> 4, tn = tid & 15;
    const int m0 = blockIdx.y * 64, n0 = blockIdx.x * 64;
    const int r = tid >> 2, q = (tid & 3) << 2;

    const int ngrp = K / (16 * ppc);
    #pragma unroll 1
    for (int i = tid; i < ngrp; i += 256) s_any[i] = gany[i];

    float c[4][4];
    #pragma unroll
    for (int i = 0; i < 4; i++)
        #pragma unroll
        for (int j = 0; j < 4; j++) c[i][j] = 0.f;

    __syncthreads();

    for (int k0 = 0; k0 < K; k0 += 16) {
        int g1 = (k0 / ppc) >> 4;
        int g2 = ((k0 + 15) / ppc) >> 4;
        if (!(s_any[g1] | s_any[g2])) continue;   // uniform smem check

        uchar4 av = *reinterpret_cast<const uchar4*>(&A[(m0 + r) * K + k0 + q]);
        As[q+0][r] = (float)av.x; As[q+1][r] = (float)av.y;
        As[q+2][r] = (float)av.z; As[q+3][r] = (float)av.w;
        int f = av.x | av.y | av.z | av.w;
        if (__syncthreads_or(f)) {
            float4 bv = *reinterpret_cast<const float4*>(&B[(n0 + r) * K + k0 + q]);
            Bs[q+0][r] = bv.x; Bs[q+1][r] = bv.y; Bs[q+2][r] = bv.z; Bs[q+3][r] = bv.w;
            __syncthreads();
            #pragma unroll
            for (int kk = 0; kk < 16; kk++) {
                float4 a = *reinterpret_cast<const float4*>(&As[kk][tm*4]);
                float4 b = *reinterpret_cast<const float4*>(&Bs[kk][tn*4]);
                c[0][0] = fmaf(a.x, b.x, c[0][0]); c[0][1] = fmaf(a.x, b.y, c[0][1]);
                c[0][2] = fmaf(a.x, b.z, c[0][2]); c[0][3] = fmaf(a.x, b.w, c[0][3]);
                c[1][0] = fmaf(a.y, b.x, c[1][0]); c[1][1] = fmaf(a.y, b.y, c[1][1]);
                c[1][2] = fmaf(a.y, b.z, c[1][2]); c[1][3] = fmaf(a.y, b.w, c[1][3]);
                c[2][0] = fmaf(a.z, b.x, c[2][0]); c[2][1] = fmaf(a.z, b.y, c[2][1]);
                c[2][2] = fmaf(a.z, b.z, c[2][2]); c[2][3] = fmaf(a.z, b.w, c[2][3]);
                c[3][0] = fmaf(a.w, b.x, c[3][0]); c[3][1] = fmaf(a.w, b.y, c[3][1]);
                c[3][2] = fmaf(a.w, b.z, c[3][2]); c[3][3] = fmaf(a.w, b.w, c[3][3]);
            }
            __syncthreads();
        }
    }
    #pragma unroll
    for (int i = 0; i < 4; i++)
        #pragma unroll
        for (int j = 0; j < 4; j++)
            C[(m0 + tm*4 + i) * N + n0 + tn*4 + j] = c[i][j];
}

// ---------------------------------------------------------------------------
// IF scan for FC layers. Writes u8 spikes + global per-16-feature any flags.
// MEAN_OUT: emit firing rate (final layer, float out, no flags).
// ---------------------------------------------------------------------------
template <bool MEAN_OUT, typename OutT>
__global__ void if_kernel(const float* __restrict__ z, OutT* __restrict__ s,
                          int E, int F, u32* __restrict__ gany, float vth)
{
    int e = blockIdx.x * blockDim.x + threadIdx.x;
    if (e >= E) return;
    float v = 0.f, m = 0.f;
    u32 any = 0;
    #pragma unroll
    for (int t = 0; t < TSTEPS; t++) {
        v += z[t*E + e];
        float sp = (v >= vth) ? 1.f : 0.f;
        v -= v * sp;
        if (MEAN_OUT) m += sp;
        else { s[t*E + e] = (OutT)sp; any |= (sp != 0.f); }
    }
    if (MEAN_OUT) s[e] = (OutT)(m * (1.f / TSTEPS));
    else if (any) gany[(e % F) >> 4] = 1u;
}

// ---------------------------------------------------------------------------
// fc3: tiny (256x10, K=512) — one thread per output element.
// ---------------------------------------------------------------------------
__global__ void fc3_kernel(const u8* __restrict__ A,
                           const float* __restrict__ W,
                           float* __restrict__ C)
{
    int idx = blockIdx.x * blockDim.x + threadIdx.x;
    if (idx >= 256 * 10) return;
    int n = idx % 10, m = idx / 10;
    const u8*    ar = A + m * 512;
    const float* wr = W + n * 512;
    float a = 0.f;
    #pragma unroll 4
    for (int k = 0; k < 512; k += 4) {
        uchar4 av = *reinterpret_cast<const uchar4*>(ar + k);
        float4 wv = *reinterpret_cast<const float4*>(wr + k);
        a = fmaf((float)av.x, wv.x, a); a = fmaf((float)av.y, wv.y, a);
        a = fmaf((float)av.z, wv.z, a); a = fmaf((float)av.w, wv.w, a);
    }
    C[idx] = a;
}

// ---------------------------------------------------------------------------
extern "C" void kernel_launch(void* const* d_in, const int* in_sizes, int n_in,
                              void* d_out, int out_size)
{
    (void)in_sizes; (void)n_in; (void)out_size;
    const float* x    = (const float*)d_in[0];
    const float* w1   = (const float*)d_in[1];
    const float* b1   = (const float*)d_in[2];
    const float* w2   = (const float*)d_in[3];
    const float* b2   = (const float*)d_in[4];
    const float* w3   = (const float*)d_in[5];
    const float* b3   = (const float*)d_in[6];
    const float* w4   = (const float*)d_in[7];
    const float* b4   = (const float*)d_in[8];
    const float* w5   = (const float*)d_in[9];
    const float* b5   = (const float*)d_in[10];
    const float* fc1w = (const float*)d_in[11];
    const float* fc2w = (const float*)d_in[12];
    const float* fc3w = (const float*)d_in[13];
    float* out = (float*)d_out;

    u8 *s1,*s2,*s3,*s4,*s5,*sf1,*sf2;
    float *zf1,*zf2,*zf3;
    u32 *flags;
    cudaGetSymbolAddress((void**)&s1,  g_s1);
    cudaGetSymbolAddress((void**)&s2,  g_s2);
    cudaGetSymbolAddress((void**)&s3,  g_s3);
    cudaGetSymbolAddress((void**)&s4,  g_s4);
    cudaGetSymbolAddress((void**)&s5,  g_s5);
    cudaGetSymbolAddress((void**)&zf1, g_zf1);
    cudaGetSymbolAddress((void**)&sf1, g_sf1);
    cudaGetSymbolAddress((void**)&zf2, g_zf2);
    cudaGetSymbolAddress((void**)&sf2, g_sf2);
    cudaGetSymbolAddress((void**)&zf3, g_zf3);
    cudaGetSymbolAddress((void**)&flags, g_flags);

    u32* f1     = flags + 0;
    u32* f2     = flags + 2048;
    u32* f3     = flags + 4096;
    u32* f4     = flags + 7168;
    u32* f5     = flags + 9216;
    u32* gany5  = flags + 11264;
    u32* ganyf1 = flags + 11272;
    u32* ganyf2 = flags + 11400;
    u32* gdummy = flags + 11432;

    zero_flags<<<(NFLAGS + 255)/256, 256>>>(flags);

    // L1: conv1 once + IF with constant drive
    const int E1 = 32*128*676;
    conv1_if<<<(E1 + 255)/256, 256>>>(x, w1, b1, s1, f1, 13515.f);

    // L2: 128->128, 4x4, s2, p1, 26->13
    conv_if<128,128,26,26,13,13,4,4,2,1, 16,1,4,192>
        <<<dim3(1, 8, 32), 192>>>(s1, w2, b2, s2, f1, f2, gdummy, 71.f);

    // L3: 128->192, 3x3, s1, p1, 13->13
    conv_if<128,192,13,13,13,13,3,3,1,1, 16,1,8,192>
        <<<dim3(1, 12, 32), 192>>>(s2, w3, b3, s3, f2, f3, gdummy, 93.f);

    // L4: 192->128, 3x3, s1, p1, 13->13
    conv_if<192,128,13,13,13,13,3,3,1,1, 16,1,8,192>
        <<<dim3(1, 8, 32), 192>>>(s3, w4, b4, s4, f3, f4, gdummy, 144.f);

    // L5: 128->128, 3x3, s2, p0, 13->6  (7 images per block)
    conv_if<128,128,13,13,6,6,3,3,2,0, 16,7,4,256>
        <<<dim3(1, 8, 5), 256>>>(s4, w5, b5, s5, f4, f5, gany5, 79.f);

    // FC1: [256,4608] x [2048,4608]^T  + IF   (ppc=36: k = c*36+pos)
    gemm_nt<<<dim3(2048/64, 256/64), 256>>>(s5, fc1w, zf1, 256, 2048, 4608,
                                            gany5, 36);
    if_kernel<false, u8><<<(32*2048 + 255)/256, 256>>>(zf1, sf1, 32*2048, 2048,
                                                       ganyf1, 2475.f);

    // FC2: [256,2048] x [512,2048]^T  + IF   (ppc=1)
    gemm_nt<<<dim3(512/64, 256/64), 256>>>(sf1, fc2w, zf2, 256, 512, 2048,
                                           ganyf1, 1);
    if_kernel<false, u8><<<(32*512 + 255)/256, 256>>>(zf2, sf2, 32*512, 512,
                                                      ganyf2, 1357.f);

    // FC3 + IF + mean over T -> [32,10]
    fc3_kernel<<<(2560 + 255)/256, 256>>>(sf2, fc3w, zf3);
    if_kernel<true, float><<<(320 + 255)/256, 256>>>(zf3, out, 320, 0,
                                                     nullptr, 388.f);
}

// round 4
// speedup vs baseline: 19.9824x; 2.5296x over previous
#include <cuda_runtime.h>

// ============================================================================
// CSNN (T=8, B=32): 5 conv+IF, 3 FC+IF, firing-rate output [32,10].
// Spiking sparsity with producer-written nonzero flags. Consumers hoist flags
// into smem, build a uniform per-timestep mask, and take a FLAT no-barrier
// path when the whole block's input is zero for all timesteps.
// Spikes stored as uint8. Layout: [T][B][C][H][W], n = t*32 + b.
// ============================================================================

#define TSTEPS 8
#define BATCH  32

typedef unsigned char u8;
typedef unsigned int  u32;

// ---------------- static scratch (no cudaMalloc allowed) -------------------
__device__ u8    g_s1 [8*32*128*26*26];
__device__ u8    g_s2 [8*32*128*13*13];
__device__ u8    g_s3 [8*32*192*13*13];
__device__ u8    g_s4 [8*32*128*13*13];
__device__ u8    g_s5 [8*32*128*6*6];
__device__ float g_zf1[8*32*2048];
__device__ u8    g_sf1[8*32*2048];
__device__ float g_zf2[8*32*512];
__device__ u8    g_sf2[8*32*512];

// flag memory map (u32 words):
//  f1 @0      (256*8)   f2 @2048 (256*8)   f3 @4096 (256*12)
//  f4 @7168   (256*8)   f5 @9216 (256*8)
//  gany5  @11264 (8)    ganyf1 @11272 (128)   ganyf2 @11400 (32)
//  dummy  @11432 (32)
#define NFLAGS 11520
__device__ u32 g_flags[NFLAGS];

__global__ void zero_flags(u32* f)
{
    int i = blockIdx.x * blockDim.x + threadIdx.x;
    if (i < NFLAGS) f[i] = 0u;
}

// ---------------------------------------------------------------------------
// Layer 1 fused: conv(1ch,5x5,s1,p1) computed ONCE (input time-invariant),
// then IF scan over T with constant drive. Writes u8 spikes + flags.
// ---------------------------------------------------------------------------
__global__ void conv1_if(const float* __restrict__ x,
                         const float* __restrict__ w,
                         const float* __restrict__ b,
                         u8* __restrict__ s1, u32* __restrict__ f1, float vth)
{
    const int E = 32*128*676;
    int idx = blockIdx.x * blockDim.x + threadIdx.x;
    if (idx >= E) return;
    int pos = idx % 676;
    int oc  = (idx / 676) % 128;
    int n   = idx / (676*128);
    int oy = pos / 26, ox = pos % 26;

    float a = b[oc];
    #pragma unroll
    for (int ky = 0; ky < 5; ky++) {
        int iy = oy + ky - 1;
        if (iy < 0 || iy >= 28) continue;
        #pragma unroll
        for (int kx = 0; kx < 5; kx++) {
            int ix = ox + kx - 1;
            if (ix < 0 || ix >= 28) continue;
            a = fmaf(__ldg(&x[(n*28 + iy)*28 + ix]),
                     __ldg(&w[(oc*5 + ky)*5 + kx]), a);
        }
    }

    float v = 0.f;
    #pragma unroll
    for (int t = 0; t < TSTEPS; t++) {
        v += a;
        float sp = (v >= vth) ? 1.f : 0.f;
        v -= v * sp;
        s1[t*E + idx] = (u8)sp;
        if (sp != 0.f)
            atomicOr(&f1[(t*BATCH + n)*8 + (oc >> 4)], 1u);
    }
}

// ---------------------------------------------------------------------------
// Fused conv + IF for layers 2..5.
//  - hoist all input flags into smem (parallel), build uniform tmask
//  - tmask==0  -> flat path: bias-only IF scan, coalesced stores, no barriers
//  - otherwise -> tiled conv path, skipping zero timesteps / chunks
// ---------------------------------------------------------------------------
template <int CIN, int COUT, int IH, int IW, int OH, int OW,
          int KH, int KW, int S, int PAD, int TC, int IPB, int CC, int NT>
__global__ __launch_bounds__(NT) void conv_if(
    const u8* __restrict__ in, const float* __restrict__ wgt,
    const float* __restrict__ bias, u8* __restrict__ sout,
    const u32* __restrict__ fin, u32* __restrict__ fout,
    u32* __restrict__ gany, float vth)
{
    constexpr int P     = OH * OW;
    constexpr int PIH   = (OH - 1) * S + KH;
    constexpr int PIW   = (OW - 1) * S + KW;
    constexpr int KK    = KH * KW;
    constexpr int KWPAD = (KK + 3) & ~3;
    constexpr int GIN   = CIN / 16;
    constexpr int GOUT  = COUT / 16;

    __shared__ float s_in[IPB][CC][PIH * PIW];
    __shared__ __align__(16) float s_w[CC][TC][KWPAD];
    __shared__ u32 s_f[IPB];
    __shared__ u32 s_fin[TSTEPS][GIN];

    const int tid = threadIdx.x;
    const int oc0 = blockIdx.y * TC;
    const int b0  = blockIdx.z * IPB;

    // ---- hoist input flags for all timesteps (parallel, once) ----
    #pragma unroll 1
    for (int i = tid; i < TSTEPS * GIN; i += NT) {
        int tt = i / GIN, gg = i - tt * GIN;
        u32 z = 0;
        #pragma unroll
        for (int im = 0; im < IPB; im++)
            if (b0 + im < BATCH)
                z |= fin[((tt*BATCH) + b0 + im) * GIN + gg];
        s_fin[tt][gg] = z;
    }
    __syncthreads();

    // uniform per-timestep nonzero mask
    u32 tmask = 0;
    #pragma unroll
    for (int tt = 0; tt < TSTEPS; tt++) {
        u32 z = 0;
        #pragma unroll
        for (int gg = 0; gg < GIN; gg++) z |= s_fin[tt][gg];
        tmask |= (z ? 1u : 0u) << tt;
    }

    if (tmask == 0u) {
        // ================= FLAT PATH: bias-only IF, no barriers =============
        #pragma unroll 1
        for (int e = tid; e < IPB * TC * P; e += NT) {
            int im  = e / (TC * P);
            int rem = e - im * (TC * P);
            int oc  = rem / P;
            int pos = rem - oc * P;
            int b   = b0 + im;
            if (b >= BATCH) break;      // im monotone in e
            float bv = __ldg(&bias[oc0 + oc]);
            float v = 0.f;
            #pragma unroll
            for (int t = 0; t < TSTEPS; t++) {
                v += bv;
                float sp = (v >= vth) ? 1.f : 0.f;
                v -= v * sp;
                sout[(((t*BATCH + b) * COUT) + oc0 + oc) * P + pos] = (u8)sp;
                if (sp != 0.f) {
                    atomicOr(&fout[(t*BATCH + b) * GOUT + (oc0 >> 4)], 1u);
                    gany[oc0 >> 4] = 1u;
                }
            }
        }
        return;
    }

    // ==================== TILED CONV PATH ===================================
    const int img_sub = tid / P;
    const int pos     = tid - img_sub * P;
    const int oy      = pos / OW;
    const int ox      = pos - oy * OW;
    const bool active = (img_sub < IPB) && (b0 + img_sub < BATCH);

    float bi[TC];
    #pragma unroll
    for (int i = 0; i < TC; i++) bi[i] = bias[oc0 + i];

    float v[TC];
    #pragma unroll
    for (int i = 0; i < TC; i++) v[i] = 0.f;

    for (int t = 0; t < TSTEPS; t++) {
        const int n_base = t * BATCH + b0;
        if (tid < IPB) s_f[tid] = 0u;
        __syncthreads();

        float acc[TC];
        #pragma unroll
        for (int i = 0; i < TC; i++) acc[i] = 0.f;

        if ((tmask >> t) & 1u) {
            #pragma unroll 1
            for (int c0 = 0; c0 < CIN; c0 += CC) {
                if (!s_fin[t][c0 >> 4]) continue;

                constexpr int LOAD = IPB * CC * PIH * PIW;
                #pragma unroll 1
                for (int i = tid; i < LOAD; i += NT) {
                    int im  = i / (CC * PIH * PIW);
                    int rem = i - im * (CC * PIH * PIW);
                    int cc  = rem / (PIH * PIW);
                    int pp  = rem - cc * (PIH * PIW);
                    int py  = pp / PIW;
                    int px  = pp - py * PIW;
                    int iy  = py - PAD, ix = px - PAD;
                    int bim = b0 + im;
                    float val = 0.f;
                    if (bim < BATCH && iy >= 0 && iy < IH && ix >= 0 && ix < IW)
                        val = (float)in[(((t*BATCH + bim) * CIN + (c0 + cc)) * IH + iy) * IW + ix];
                    s_in[im][cc][pp] = val;
                }
                constexpr int WLOAD = CC * TC * KK;
                #pragma unroll 1
                for (int i = tid; i < WLOAD; i += NT) {
                    int cc  = i / (TC * KK);
                    int rem = i - cc * (TC * KK);
                    int oc  = rem / KK;
                    int k   = rem - oc * KK;
                    s_w[cc][oc][k] = wgt[((oc0 + oc) * CIN + (c0 + cc)) * KK + k];
                }
                __syncthreads();
                if (active) {
                    #pragma unroll
                    for (int cc = 0; cc < CC; cc++) {
                        float xin[KK];
                        #pragma unroll
                        for (int ky = 0; ky < KH; ky++)
                            #pragma unroll
                            for (int kx = 0; kx < KW; kx++)
                                xin[ky*KW + kx] =
                                    s_in[img_sub][cc][(oy*S + ky)*PIW + ox*S + kx];
                        #pragma unroll
                        for (int oc = 0; oc < TC; oc++) {
                            float w[KWPAD];
                            #pragma unroll
                            for (int q = 0; q < KWPAD/4; q++) {
                                float4 v4 = *reinterpret_cast<const float4*>(&s_w[cc][oc][q*4]);
                                w[q*4+0] = v4.x; w[q*4+1] = v4.y;
                                w[q*4+2] = v4.z; w[q*4+3] = v4.w;
                            }
                            float a = acc[oc];
                            #pragma unroll
                            for (int k = 0; k < KK; k++)
                                a = fmaf(xin[k], w[k], a);
                            acc[oc] = a;
                        }
                    }
                }
                __syncthreads();
            }
        }

        if (active) {
            int n = n_base + img_sub;
            u32 any = 0;
            #pragma unroll
            for (int oc = 0; oc < TC; oc++) {
                v[oc] += acc[oc] + bi[oc];
                float sp = (v[oc] >= vth) ? 1.f : 0.f;
                v[oc] -= v[oc] * sp;
                sout[(n * COUT + oc0 + oc) * P + pos] = (u8)sp;
                any |= (sp != 0.f);
            }
            if (any) s_f[img_sub] = 1u;
        }
        __syncthreads();
        if (tid < IPB && b0 + tid < BATCH && s_f[tid]) {
            fout[(n_base + tid) * GOUT + (oc0 >> 4)] = 1u;
            gany[oc0 >> 4] = 1u;
        }
    }
}

// ---------------------------------------------------------------------------
// SGEMM C[M,N] = A[M,K](u8 spikes) * B[N,K]^T (float weights).
// 64x64x16 tiles, 256 threads, 4x4 micro-tile.
// Coarse skip via global any-flags; if ALL groups zero -> flat zero-store.
// ---------------------------------------------------------------------------
__global__ __launch_bounds__(256) void gemm_nt(
    const u8* __restrict__ A, const float* __restrict__ B,
    float* __restrict__ C, int M, int N, int K,
    const u32* __restrict__ gany, int ppc)
{
    __shared__ float As[16][64];
    __shared__ float Bs[16][64];
    __shared__ u32 s_any[128];
    const int tid = threadIdx.x;
    const int tm = tid >> 4, tn = tid & 15;
    const int m0 = blockIdx.y * 64, n0 = blockIdx.x * 64;
    const int r = tid >> 2, q = (tid & 3) << 2;

    const int ngrp = K / (16 * ppc);
    #pragma unroll 1
    for (int i = tid; i < ngrp; i += 256) s_any[i] = gany[i];
    __syncthreads();

    u32 anyall = 0;
    #pragma unroll 1
    for (int i = 0; i < ngrp; i++) anyall |= s_any[i];

    if (!anyall) {
        // flat path: C tile is exactly zero
        #pragma unroll
        for (int i = 0; i < 4; i++) {
            float4 z = make_float4(0.f, 0.f, 0.f, 0.f);
            *reinterpret_cast<float4*>(&C[(m0 + tm*4 + i) * N + n0 + tn*4]) = z;
        }
        return;
    }

    float c[4][4];
    #pragma unroll
    for (int i = 0; i < 4; i++)
        #pragma unroll
        for (int j = 0; j < 4; j++) c[i][j] = 0.f;

    for (int k0 = 0; k0 < K; k0 += 16) {
        int g1 = (k0 / ppc) >> 4;
        int g2 = ((k0 + 15) / ppc) >> 4;
        if (!(s_any[g1] | s_any[g2])) continue;

        uchar4 av = *reinterpret_cast<const uchar4*>(&A[(m0 + r) * K + k0 + q]);
        As[q+0][r] = (float)av.x; As[q+1][r] = (float)av.y;
        As[q+2][r] = (float)av.z; As[q+3][r] = (float)av.w;
        int f = av.x | av.y | av.z | av.w;
        if (__syncthreads_or(f)) {
            float4 bv = *reinterpret_cast<const float4*>(&B[(n0 + r) * K + k0 + q]);
            Bs[q+0][r] = bv.x; Bs[q+1][r] = bv.y; Bs[q+2][r] = bv.z; Bs[q+3][r] = bv.w;
            __syncthreads();
            #pragma unroll
            for (int kk = 0; kk < 16; kk++) {
                float4 a = *reinterpret_cast<const float4*>(&As[kk][tm*4]);
                float4 b = *reinterpret_cast<const float4*>(&Bs[kk][tn*4]);
                c[0][0] = fmaf(a.x, b.x, c[0][0]); c[0][1] = fmaf(a.x, b.y, c[0][1]);
                c[0][2] = fmaf(a.x, b.z, c[0][2]); c[0][3] = fmaf(a.x, b.w, c[0][3]);
                c[1][0] = fmaf(a.y, b.x, c[1][0]); c[1][1] = fmaf(a.y, b.y, c[1][1]);
                c[1][2] = fmaf(a.y, b.z, c[1][2]); c[1][3] = fmaf(a.y, b.w, c[1][3]);
                c[2][0] = fmaf(a.z, b.x, c[2][0]); c[2][1] = fmaf(a.z, b.y, c[2][1]);
                c[2][2] = fmaf(a.z, b.z, c[2][2]); c[2][3] = fmaf(a.z, b.w, c[2][3]);
                c[3][0] = fmaf(a.w, b.x, c[3][0]); c[3][1] = fmaf(a.w, b.y, c[3][1]);
                c[3][2] = fmaf(a.w, b.z, c[3][2]); c[3][3] = fmaf(a.w, b.w, c[3][3]);
            }
            __syncthreads();
        }
    }
    #pragma unroll
    for (int i = 0; i < 4; i++)
        #pragma unroll
        for (int j = 0; j < 4; j++)
            C[(m0 + tm*4 + i) * N + n0 + tn*4 + j] = c[i][j];
}

// ---------------------------------------------------------------------------
// IF scan for FC layers. Writes u8 spikes + global per-16-feature any flags.
// ---------------------------------------------------------------------------
__global__ void if_kernel(const float* __restrict__ z, u8* __restrict__ s,
                          int E, int F, u32* __restrict__ gany, float vth)
{
    int e = blockIdx.x * blockDim.x + threadIdx.x;
    if (e >= E) return;
    float v = 0.f;
    u32 any = 0;
    #pragma unroll
    for (int t = 0; t < TSTEPS; t++) {
        v += z[t*E + e];
        float sp = (v >= vth) ? 1.f : 0.f;
        v -= v * sp;
        s[t*E + e] = (u8)sp;
        any |= (sp != 0.f);
    }
    if (any) gany[(e % F) >> 4] = 1u;
}

// ---------------------------------------------------------------------------
// Fused fc3 + final IF + mean: each thread owns one (b, class), computes the
// 8 per-timestep dot products (K=512) and the IF scan, writes firing rate.
// All-zero shortcut via ganyf2 (no bias in FC -> zf3 == 0 -> rate 0).
// ---------------------------------------------------------------------------
__global__ void fc3_if(const u8* __restrict__ A, const float* __restrict__ W,
                       float* __restrict__ out, const u32* __restrict__ gany,
                       float vth)
{
    int idx = blockIdx.x * blockDim.x + threadIdx.x;
    if (idx >= 320) return;
    int cls = idx % 10, b = idx / 10;

    u32 anyall = 0;
    #pragma unroll
    for (int i = 0; i < 32; i++) anyall |= __ldg(&gany[i]);

    float m = 0.f;
    if (anyall) {
        const float* wr = W + cls * 512;
        float v = 0.f;
        #pragma unroll 1
        for (int t = 0; t < TSTEPS; t++) {
            const u8* ar = A + (t*BATCH + b) * 512;
            float d = 0.f;
            #pragma unroll 4
            for (int k = 0; k < 512; k += 4) {
                uchar4 av = *reinterpret_cast<const uchar4*>(ar + k);
                float4 wv = *reinterpret_cast<const float4*>(wr + k);
                d = fmaf((float)av.x, wv.x, d); d = fmaf((float)av.y, wv.y, d);
                d = fmaf((float)av.z, wv.z, d); d = fmaf((float)av.w, wv.w, d);
            }
            v += d;
            float sp = (v >= vth) ? 1.f : 0.f;
            v -= v * sp;
            m += sp;
        }
    }
    out[b*10 + cls] = m * (1.f / TSTEPS);
}

// ---------------------------------------------------------------------------
extern "C" void kernel_launch(void* const* d_in, const int* in_sizes, int n_in,
                              void* d_out, int out_size)
{
    (void)in_sizes; (void)n_in; (void)out_size;
    const float* x    = (const float*)d_in[0];
    const float* w1   = (const float*)d_in[1];
    const float* b1   = (const float*)d_in[2];
    const float* w2   = (const float*)d_in[3];
    const float* b2   = (const float*)d_in[4];
    const float* w3   = (const float*)d_in[5];
    const float* b3   = (const float*)d_in[6];
    const float* w4   = (const float*)d_in[7];
    const float* b4   = (const float*)d_in[8];
    const float* w5   = (const float*)d_in[9];
    const float* b5   = (const float*)d_in[10];
    const float* fc1w = (const float*)d_in[11];
    const float* fc2w = (const float*)d_in[12];
    const float* fc3w = (const float*)d_in[13];
    float* out = (float*)d_out;

    u8 *s1,*s2,*s3,*s4,*s5,*sf1,*sf2;
    float *zf1,*zf2;
    u32 *flags;
    cudaGetSymbolAddress((void**)&s1,  g_s1);
    cudaGetSymbolAddress((void**)&s2,  g_s2);
    cudaGetSymbolAddress((void**)&s3,  g_s3);
    cudaGetSymbolAddress((void**)&s4,  g_s4);
    cudaGetSymbolAddress((void**)&s5,  g_s5);
    cudaGetSymbolAddress((void**)&zf1, g_zf1);
    cudaGetSymbolAddress((void**)&sf1, g_sf1);
    cudaGetSymbolAddress((void**)&zf2, g_zf2);
    cudaGetSymbolAddress((void**)&sf2, g_sf2);
    cudaGetSymbolAddress((void**)&flags, g_flags);

    u32* f1     = flags + 0;
    u32* f2     = flags + 2048;
    u32* f3     = flags + 4096;
    u32* f4     = flags + 7168;
    u32* f5     = flags + 9216;
    u32* gany5  = flags + 11264;
    u32* ganyf1 = flags + 11272;
    u32* ganyf2 = flags + 11400;
    u32* gdummy = flags + 11432;

    zero_flags<<<(NFLAGS + 255)/256, 256>>>(flags);

    // L1: conv1 once + IF with constant drive
    const int E1 = 32*128*676;
    conv1_if<<<(E1 + 255)/256, 256>>>(x, w1, b1, s1, f1, 13515.f);

    // L2: 128->128, 4x4, s2, p1, 26->13
    conv_if<128,128,26,26,13,13,4,4,2,1, 16,1,4,192>
        <<<dim3(1, 8, 32), 192>>>(s1, w2, b2, s2, f1, f2, gdummy, 71.f);

    // L3: 128->192, 3x3, s1, p1, 13->13
    conv_if<128,192,13,13,13,13,3,3,1,1, 16,1,8,192>
        <<<dim3(1, 12, 32), 192>>>(s2, w3, b3, s3, f2, f3, gdummy, 93.f);

    // L4: 192->128, 3x3, s1, p1, 13->13
    conv_if<192,128,13,13,13,13,3,3,1,1, 16,1,8,192>
        <<<dim3(1, 8, 32), 192>>>(s3, w4, b4, s4, f3, f4, gdummy, 144.f);

    // L5: 128->128, 3x3, s2, p0, 13->6  (7 images per block)
    conv_if<128,128,13,13,6,6,3,3,2,0, 16,7,4,256>
        <<<dim3(1, 8, 5), 256>>>(s4, w5, b5, s5, f4, f5, gany5, 79.f);

    // FC1: [256,4608] x [2048,4608]^T  + IF   (ppc=36)
    gemm_nt<<<dim3(2048/64, 256/64), 256>>>(s5, fc1w, zf1, 256, 2048, 4608,
                                            gany5, 36);
    if_kernel<<<(32*2048 + 255)/256, 256>>>(zf1, sf1, 32*2048, 2048,
                                            ganyf1, 2475.f);

    // FC2: [256,2048] x [512,2048]^T  + IF   (ppc=1)
    gemm_nt<<<dim3(512/64, 256/64), 256>>>(sf1, fc2w, zf2, 256, 512, 2048,
                                           ganyf1, 1);
    if_kernel<<<(32*512 + 255)/256, 256>>>(zf2, sf2, 32*512, 512,
                                           ganyf2, 1357.f);

    // FC3 + final IF + mean -> [32,10]
    fc3_if<<<2, 160>>>(sf2, fc3w, out, ganyf2, 388.f);
}

// round 5
// speedup vs baseline: 28.2432x; 1.4134x over previous
#include <cuda_runtime.h>

// ============================================================================
// CSNN (T=8, B=32): 5 conv+IF, 3 FC+IF, firing-rate output [32,10].
// Sparse-valid spike tensors: per-channel u8 validity flags are the contract.
// Producers write spike planes ONLY for flagged (t,n,channel); consumers
// zero-fill unflagged channels at load. All-zero network => no spike traffic.
// Layout: [T][B][C][H][W] row-major, n = t*32 + b.
// ============================================================================

#define TSTEPS 8
#define BATCH  32

typedef unsigned char u8;
typedef unsigned int  u32;

// ---------------- static scratch (no cudaMalloc allowed) -------------------
__device__ u8    g_s1 [8*32*128*26*26];
__device__ u8    g_s2 [8*32*128*13*13];
__device__ u8    g_s3 [8*32*192*13*13];
__device__ u8    g_s4 [8*32*128*13*13];
__device__ u8    g_s5 [8*32*128*6*6];
__device__ float g_zf1[8*32*2048];
__device__ u8    g_sf1[8*32*2048];
__device__ float g_zf2[8*32*512];
__device__ u8    g_sf2[8*32*512];

// per-channel validity flags (u8 per (n, c)), written unconditionally by the
// owning producer block every run -> no zeroing needed.
__device__ u8 g_f1[256*128];
__device__ u8 g_f2[256*128];
__device__ u8 g_f3[256*192];
__device__ u8 g_f4[256*128];

// global any-flags (atomic-ish accumulation -> zeroed each run in conv1_if)
//  gany5 @0 (8 words: per 16-ch group of s5), ganyf1 @8 (128), ganyf2 @136 (32)
#define NGZ 168
__device__ u32 g_gz[NGZ];

// ---------------------------------------------------------------------------
// Layer 1: conv(1ch,5x5,s1,p1) once (time-invariant input) + IF over T.
// Block = (image n, 4 output channels). Writes flags unconditionally; writes
// spike planes only for flagged (t, oc). Also zeroes the gany words.
// ---------------------------------------------------------------------------
#define NT1 704
__global__ __launch_bounds__(NT1) void conv1_if(
    const float* __restrict__ x, const float* __restrict__ w,
    const float* __restrict__ b, u8* __restrict__ s1, u8* __restrict__ f1,
    u32* __restrict__ gz, float vth)
{
    __shared__ float sx[30*30];
    __shared__ float sw[4*25];
    __shared__ float sb[4];
    const int tid = threadIdx.x;
    const int n   = blockIdx.x;
    const int oc0 = blockIdx.y * 4;

    if (blockIdx.x == 0 && blockIdx.y == 0 && tid < NGZ) gz[tid] = 0u;

    // padded input plane (pad=1 low, extra high cols are never read)
    #pragma unroll 1
    for (int i = tid; i < 900; i += NT1) {
        int r = i / 30, c = i - r * 30;
        float v = 0.f;
        if (r >= 1 && r < 29 && c >= 1 && c < 29)
            v = x[n*784 + (r-1)*28 + (c-1)];
        sx[i] = v;
    }
    if (tid < 100) sw[tid] = w[oc0*25 + tid];
    if (tid < 4)   sb[tid] = b[oc0 + tid];
    __syncthreads();

    u32 mymask = 0;                 // bit (oc*8 + t)
    const int pos = tid;
    if (pos < 676) {
        int oy = pos / 26, ox = pos - (pos/26)*26;
        float a[4];
        #pragma unroll
        for (int oc = 0; oc < 4; oc++) a[oc] = sb[oc];
        #pragma unroll
        for (int ky = 0; ky < 5; ky++)
            #pragma unroll
            for (int kx = 0; kx < 5; kx++) {
                float xv = sx[(oy+ky)*30 + ox+kx];
                #pragma unroll
                for (int oc = 0; oc < 4; oc++)
                    a[oc] = fmaf(xv, sw[oc*25 + ky*5 + kx], a[oc]);
            }
        #pragma unroll
        for (int oc = 0; oc < 4; oc++) {
            float v = 0.f;
            #pragma unroll
            for (int t = 0; t < TSTEPS; t++) {
                v += a[oc];
                float sp = (v >= vth) ? 1.f : 0.f;
                v -= v * sp;
                if (sp != 0.f) mymask |= 1u << (oc*8 + t);
            }
        }
    }
    u32 m = (u32)__syncthreads_or((int)mymask);

    // flags (unconditional, per (t, oc))
    if (tid < 32) {
        int t = tid >> 2, oc = tid & 3;
        f1[(t*BATCH + n)*128 + oc0 + oc] = (u8)((m >> (oc*8 + t)) & 1u);
    }
    // gated spike stores
    if (pos < 676 && m) {
        #pragma unroll
        for (int oc = 0; oc < 4; oc++) {
            u32 blk = (m >> (oc*8)) & 0xFFu;
            if (!blk) continue;
            #pragma unroll
            for (int t = 0; t < TSTEPS; t++)
                if ((blk >> t) & 1u)
                    s1[((size_t)(t*BATCH + n)*128 + oc0 + oc)*676 + pos] =
                        (u8)((mymask >> (oc*8 + t)) & 1u);
        }
    }
}

// ---------------------------------------------------------------------------
// Fused conv + IF, layers 2..5. Block = (16-oc tile, one image).
// GATED=true : flag-gated spike stores + flag writes (layers 2-4)
// GATED=false: unconditional stores + global gany per 16-oc group (layer 5)
// Consumers zero-fill unflagged input channels; zero chunks/timesteps skipped.
// ---------------------------------------------------------------------------
template <int CIN, int COUT, int IH, int IW, int OH, int OW,
          int KH, int KW, int S, int PAD, int TC, int CC, int NT, bool GATED>
__global__ __launch_bounds__(NT) void conv_if(
    const u8* __restrict__ in, const float* __restrict__ wgt,
    const float* __restrict__ bias, u8* __restrict__ sout,
    const u8* __restrict__ fin, u8* __restrict__ fout,
    u32* __restrict__ gany, float vth)
{
    constexpr int P     = OH * OW;
    constexpr int PIH   = (OH - 1) * S + KH;
    constexpr int PIW   = (OW - 1) * S + KW;
    constexpr int KK    = KH * KW;
    constexpr int KWPAD = (KK + 3) & ~3;
    constexpr int FW    = TSTEPS * CIN / 4;

    __shared__ float s_in[CC][PIH * PIW];
    __shared__ __align__(16) float s_w[CC][TC][KWPAD];
    __shared__ u32 s_finw[FW];
    const u8* s_finb = (const u8*)s_finw;

    const int tid = threadIdx.x;
    const int oc0 = blockIdx.y * TC;
    const int b0  = blockIdx.z;

    // hoist per-channel flags for all timesteps (u32-packed)
    #pragma unroll 1
    for (int i = tid; i < FW; i += NT) {
        int t = i / (CIN/4), off = i - t*(CIN/4);
        s_finw[i] = ((const u32*)fin)[((t*BATCH + b0)*CIN)/4 + off];
    }
    __syncthreads();

    // per-timestep nonzero mask (cooperative)
    u32 part = 0;
    #pragma unroll 1
    for (int i = tid; i < FW; i += NT)
        if (s_finw[i]) part |= 1u << (i / (CIN/4));
    u32 tmask = (u32)__syncthreads_or((int)part);

    float bi[TC];
    #pragma unroll
    for (int i = 0; i < TC; i++) bi[i] = __ldg(&bias[oc0 + i]);

    if (tmask == 0u) {
        // ============ FLAT PATH: bias-only IF (uniform across positions) ====
        u32 spb[TC]; u32 anyb = 0;
        #pragma unroll
        for (int oc = 0; oc < TC; oc++) {
            float v = 0.f; u32 bits = 0;
            #pragma unroll
            for (int t = 0; t < TSTEPS; t++) {
                v += bi[oc];
                float sp = (v >= vth) ? 1.f : 0.f;
                v -= v * sp;
                if (sp != 0.f) bits |= 1u << t;
            }
            spb[oc] = bits; anyb |= bits;
        }
        if (GATED) {
            #pragma unroll 1
            for (int i = tid; i < TSTEPS*TC; i += NT) {
                int t = i / TC, oc = i - t*TC;
                fout[(t*BATCH + b0)*COUT + oc0 + oc] = (u8)((spb[oc] >> t) & 1u);
            }
            if (anyb) {
                #pragma unroll 1
                for (int oc = 0; oc < TC; oc++) {
                    if (!spb[oc]) continue;
                    for (int t = 0; t < TSTEPS; t++)
                        if ((spb[oc] >> t) & 1u)
                            for (int p = tid; p < P; p += NT)
                                sout[((size_t)(t*BATCH + b0)*COUT + oc0 + oc)*P + p] = 1;
                }
            }
        } else {
            #pragma unroll 1
            for (int i = tid; i < TSTEPS*TC*P; i += NT) {
                int t   = i / (TC*P);
                int rem = i - t*(TC*P);
                int oc  = rem / P;
                int p   = rem - oc*P;
                sout[((size_t)(t*BATCH + b0)*COUT + oc0 + oc)*P + p] =
                    (u8)((spb[oc] >> t) & 1u);
            }
            if (anyb && tid == 0) gany[oc0 >> 4] = 1u;
        }
        return;
    }

    // =================== TILED CONV PATH ====================================
    const int pos = tid;
    const bool active = pos < P;
    const int oy = pos / OW;
    const int ox = pos - oy * OW;

    float v[TC];
    #pragma unroll
    for (int i = 0; i < TC; i++) v[i] = 0.f;

    for (int t = 0; t < TSTEPS; t++) {
        float acc[TC];
        #pragma unroll
        for (int i = 0; i < TC; i++) acc[i] = 0.f;

        if ((tmask >> t) & 1u) {
            #pragma unroll 1
            for (int c0 = 0; c0 < CIN; c0 += CC) {
                u32 cz = 0;
                #pragma unroll
                for (int q = 0; q < CC/4; q++)
                    cz |= s_finw[(t*CIN + c0)/4 + q];
                if (!cz) continue;

                #pragma unroll 1
                for (int i = tid; i < CC*PIH*PIW; i += NT) {
                    int cc = i / (PIH*PIW);
                    int pp = i - cc*(PIH*PIW);
                    int py = pp / PIW;
                    int px = pp - py*PIW;
                    int iy = py - PAD, ix = px - PAD;
                    float val = 0.f;
                    if (s_finb[t*CIN + c0 + cc] &&
                        iy >= 0 && iy < IH && ix >= 0 && ix < IW)
                        val = (float)in[((size_t)(t*BATCH + b0)*CIN + c0 + cc)*(IH*IW)
                                        + iy*IW + ix];
                    s_in[cc][pp] = val;
                }
                #pragma unroll 1
                for (int i = tid; i < CC*TC*KK; i += NT) {
                    int cc  = i / (TC*KK);
                    int rem = i - cc*(TC*KK);
                    int oc  = rem / KK;
                    int k   = rem - oc*KK;
                    s_w[cc][oc][k] = wgt[((oc0 + oc)*CIN + c0 + cc)*KK + k];
                }
                __syncthreads();
                if (active) {
                    #pragma unroll
                    for (int cc = 0; cc < CC; cc++) {
                        float xin[KK];
                        #pragma unroll
                        for (int ky = 0; ky < KH; ky++)
                            #pragma unroll
                            for (int kx = 0; kx < KW; kx++)
                                xin[ky*KW + kx] = s_in[cc][(oy*S + ky)*PIW + ox*S + kx];
                        #pragma unroll
                        for (int oc = 0; oc < TC; oc++) {
                            float wv[KWPAD];
                            #pragma unroll
                            for (int q = 0; q < KWPAD/4; q++) {
                                float4 v4 = *reinterpret_cast<const float4*>(&s_w[cc][oc][q*4]);
                                wv[q*4+0] = v4.x; wv[q*4+1] = v4.y;
                                wv[q*4+2] = v4.z; wv[q*4+3] = v4.w;
                            }
                            float a = acc[oc];
                            #pragma unroll
                            for (int k = 0; k < KK; k++)
                                a = fmaf(xin[k], wv[k], a);
                            acc[oc] = a;
                        }
                    }
                }
                __syncthreads();
            }
        }

        // IF update; block-wide per-oc spike mask
        u32 myspk = 0;
        if (active) {
            #pragma unroll
            for (int oc = 0; oc < TC; oc++) {
                v[oc] += acc[oc] + bi[oc];
                float sp = (v[oc] >= vth) ? 1.f : 0.f;
                v[oc] -= v[oc] * sp;
                if (sp != 0.f) myspk |= 1u << oc;
            }
        }
        u32 bm = (u32)__syncthreads_or((int)myspk);

        if (GATED) {
            if (tid < TC)
                fout[(t*BATCH + b0)*COUT + oc0 + tid] = (u8)((bm >> tid) & 1u);
            if (active && bm) {
                #pragma unroll
                for (int oc = 0; oc < TC; oc++)
                    if ((bm >> oc) & 1u)
                        sout[((size_t)(t*BATCH + b0)*COUT + oc0 + oc)*P + pos] =
                            (u8)((myspk >> oc) & 1u);
            }
        } else {
            if (active) {
                #pragma unroll
                for (int oc = 0; oc < TC; oc++)
                    sout[((size_t)(t*BATCH + b0)*COUT + oc0 + oc)*P + pos] =
                        (u8)((myspk >> oc) & 1u);
            }
            if (bm && tid == 0) gany[oc0 >> 4] = 1u;
        }
    }
}

// ---------------------------------------------------------------------------
// SGEMM C[M,N] = A[M,K](u8) * B[N,K]^T. 64x64x16 tiles, 4x4 micro-tile.
// All-zero input (via gany) -> exit without writing C (paired if_kernel
// checks the same flags). Per-group chunk skip + per-tile syncthreads_or.
// ---------------------------------------------------------------------------
__global__ __launch_bounds__(256) void gemm_nt(
    const u8* __restrict__ A, const float* __restrict__ B,
    float* __restrict__ C, int M, int N, int K,
    const u32* __restrict__ gany, int ppc, int ngrp)
{
    __shared__ float As[16][64];
    __shared__ float Bs[16][64];
    __shared__ u32 s_any[128];
    const int tid = threadIdx.x;

    u32 part = 0;
    #pragma unroll 1
    for (int i = tid; i < ngrp; i += 256) {
        u32 g = __ldg(&gany[i]);
        s_any[i] = g;
        part |= g;
    }
    u32 anyall = (u32)__syncthreads_or((int)part);
    if (!anyall) return;

    const int tm = tid >> 4, tn = tid & 15;
    const int m0 = blockIdx.y * 64, n0 = blockIdx.x * 64;
    const int r = tid >> 2, q = (tid & 3) << 2;

    float c[4][4];
    #pragma unroll
    for (int i = 0; i < 4; i++)
        #pragma unroll
        for (int j = 0; j < 4; j++) c[i][j] = 0.f;

    for (int k0 = 0; k0 < K; k0 += 16) {
        int g1 = (k0 / ppc) >> 4;
        int g2 = ((k0 + 15) / ppc) >> 4;
        if (!(s_any[g1] | s_any[g2])) continue;

        uchar4 av = *reinterpret_cast<const uchar4*>(&A[(m0 + r) * K + k0 + q]);
        As[q+0][r] = (float)av.x; As[q+1][r] = (float)av.y;
        As[q+2][r] = (float)av.z; As[q+3][r] = (float)av.w;
        int f = av.x | av.y | av.z | av.w;
        if (__syncthreads_or(f)) {
            float4 bv = *reinterpret_cast<const float4*>(&B[(n0 + r) * K + k0 + q]);
            Bs[q+0][r] = bv.x; Bs[q+1][r] = bv.y; Bs[q+2][r] = bv.z; Bs[q+3][r] = bv.w;
            __syncthreads();
            #pragma unroll
            for (int kk = 0; kk < 16; kk++) {
                float4 a = *reinterpret_cast<const float4*>(&As[kk][tm*4]);
                float4 b = *reinterpret_cast<const float4*>(&Bs[kk][tn*4]);
                c[0][0] = fmaf(a.x, b.x, c[0][0]); c[0][1] = fmaf(a.x, b.y, c[0][1]);
                c[0][2] = fmaf(a.x, b.z, c[0][2]); c[0][3] = fmaf(a.x, b.w, c[0][3]);
                c[1][0] = fmaf(a.y, b.x, c[1][0]); c[1][1] = fmaf(a.y, b.y, c[1][1]);
                c[1][2] = fmaf(a.y, b.z, c[1][2]); c[1][3] = fmaf(a.y, b.w, c[1][3]);
                c[2][0] = fmaf(a.z, b.x, c[2][0]); c[2][1] = fmaf(a.z, b.y, c[2][1]);
                c[2][2] = fmaf(a.z, b.z, c[2][2]); c[2][3] = fmaf(a.z, b.w, c[2][3]);
                c[3][0] = fmaf(a.w, b.x, c[3][0]); c[3][1] = fmaf(a.w, b.y, c[3][1]);
                c[3][2] = fmaf(a.w, b.z, c[3][2]); c[3][3] = fmaf(a.w, b.w, c[3][3]);
            }
            __syncthreads();
        }
    }
    #pragma unroll
    for (int i = 0; i < 4; i++)
        #pragma unroll
        for (int j = 0; j < 4; j++)
            C[(m0 + tm*4 + i) * N + n0 + tn*4 + j] = c[i][j];
}

// ---------------------------------------------------------------------------
// IF scan for FC layers. Hoists the SAME input gany flags the gemm used: if
// all zero, z was never written -> exit (no bias in FC => no spikes).
// Otherwise full scan; writes u8 spikes + output gany per 16-feature group.
// ---------------------------------------------------------------------------
__global__ void if_kernel(const float* __restrict__ z, u8* __restrict__ s,
                          int E, int F,
                          const u32* __restrict__ gin, int ngin,
                          u32* __restrict__ gout, float vth)
{
    u32 part = 0;
    #pragma unroll 1
    for (int i = threadIdx.x; i < ngin; i += blockDim.x)
        part |= __ldg(&gin[i]);
    u32 anyall = (u32)__syncthreads_or((int)part);
    if (!anyall) return;

    int e = blockIdx.x * blockDim.x + threadIdx.x;
    if (e >= E) return;
    float v = 0.f;
    u32 any = 0;
    #pragma unroll
    for (int t = 0; t < TSTEPS; t++) {
        v += z[t*E + e];
        float sp = (v >= vth) ? 1.f : 0.f;
        v -= v * sp;
        s[t*E + e] = (u8)sp;
        any |= (sp != 0.f);
    }
    if (any) gout[(e % F) >> 4] = 1u;
}

// ---------------------------------------------------------------------------
// Fused fc3 + final IF + mean. All-zero shortcut via ganyf2.
// ---------------------------------------------------------------------------
__global__ void fc3_if(const u8* __restrict__ A, const float* __restrict__ W,
                       float* __restrict__ out, const u32* __restrict__ gany,
                       float vth)
{
    int idx = blockIdx.x * blockDim.x + threadIdx.x;
    if (idx >= 320) return;
    int cls = idx % 10, b = idx / 10;

    u32 anyall = 0;
    #pragma unroll
    for (int i = 0; i < 32; i++) anyall |= __ldg(&gany[i]);

    float m = 0.f;
    if (anyall) {
        const float* wr = W + cls * 512;
        float v = 0.f;
        #pragma unroll 1
        for (int t = 0; t < TSTEPS; t++) {
            const u8* ar = A + (t*BATCH + b) * 512;
            float d = 0.f;
            #pragma unroll 4
            for (int k = 0; k < 512; k += 4) {
                uchar4 av = *reinterpret_cast<const uchar4*>(ar + k);
                float4 wv = *reinterpret_cast<const float4*>(wr + k);
                d = fmaf((float)av.x, wv.x, d); d = fmaf((float)av.y, wv.y, d);
                d = fmaf((float)av.z, wv.z, d); d = fmaf((float)av.w, wv.w, d);
            }
            v += d;
            float sp = (v >= vth) ? 1.f : 0.f;
            v -= v * sp;
            m += sp;
        }
    }
    out[b*10 + cls] = m * (1.f / TSTEPS);
}

// ---------------------------------------------------------------------------
extern "C" void kernel_launch(void* const* d_in, const int* in_sizes, int n_in,
                              void* d_out, int out_size)
{
    (void)in_sizes; (void)n_in; (void)out_size;
    const float* x    = (const float*)d_in[0];
    const float* w1   = (const float*)d_in[1];
    const float* b1   = (const float*)d_in[2];
    const float* w2   = (const float*)d_in[3];
    const float* b2   = (const float*)d_in[4];
    const float* w3   = (const float*)d_in[5];
    const float* b3   = (const float*)d_in[6];
    const float* w4   = (const float*)d_in[7];
    const float* b4   = (const float*)d_in[8];
    const float* w5   = (const float*)d_in[9];
    const float* b5   = (const float*)d_in[10];
    const float* fc1w = (const float*)d_in[11];
    const float* fc2w = (const float*)d_in[12];
    const float* fc3w = (const float*)d_in[13];
    float* out = (float*)d_out;

    u8 *s1,*s2,*s3,*s4,*s5,*sf1,*sf2,*f1,*f2,*f3,*f4;
    float *zf1,*zf2;
    u32 *gz;
    cudaGetSymbolAddress((void**)&s1,  g_s1);
    cudaGetSymbolAddress((void**)&s2,  g_s2);
    cudaGetSymbolAddress((void**)&s3,  g_s3);
    cudaGetSymbolAddress((void**)&s4,  g_s4);
    cudaGetSymbolAddress((void**)&s5,  g_s5);
    cudaGetSymbolAddress((void**)&zf1, g_zf1);
    cudaGetSymbolAddress((void**)&sf1, g_sf1);
    cudaGetSymbolAddress((void**)&zf2, g_zf2);
    cudaGetSymbolAddress((void**)&sf2, g_sf2);
    cudaGetSymbolAddress((void**)&f1,  g_f1);
    cudaGetSymbolAddress((void**)&f2,  g_f2);
    cudaGetSymbolAddress((void**)&f3,  g_f3);
    cudaGetSymbolAddress((void**)&f4,  g_f4);
    cudaGetSymbolAddress((void**)&gz,  g_gz);

    u32* gany5  = gz + 0;
    u32* ganyf1 = gz + 8;
    u32* ganyf2 = gz + 136;

    // L1: conv1 once + IF (also zeroes gany words)
    conv1_if<<<dim3(32, 32), NT1>>>(x, w1, b1, s1, f1, gz, 13515.f);

    // L2: 128->128, 4x4, s2, p1, 26->13
    conv_if<128,128,26,26,13,13,4,4,2,1, 16,4,192,true>
        <<<dim3(1, 8, 32), 192>>>(s1, w2, b2, s2, f1, f2, nullptr, 71.f);

    // L3: 128->192, 3x3, s1, p1, 13->13
    conv_if<128,192,13,13,13,13,3,3,1,1, 16,8,192,true>
        <<<dim3(1, 12, 32), 192>>>(s2, w3, b3, s3, f2, f3, nullptr, 93.f);

    // L4: 192->128, 3x3, s1, p1, 13->13
    conv_if<192,128,13,13,13,13,3,3,1,1, 16,8,192,true>
        <<<dim3(1, 8, 32), 192>>>(s3, w4, b4, s4, f3, f4, nullptr, 144.f);

    // L5: 128->128, 3x3, s2, p0, 13->6 (unconditional stores, sets gany5)
    conv_if<128,128,13,13,6,6,3,3,2,0, 16,4,64,false>
        <<<dim3(1, 8, 32), 64>>>(s4, w5, b5, s5, f4, nullptr, gany5, 79.f);

    // FC1: [256,4608] x [2048,4608]^T + IF  (ppc=36, 8 groups)
    gemm_nt<<<dim3(32, 4), 256>>>(s5, fc1w, zf1, 256, 2048, 4608, gany5, 36, 8);
    if_kernel<<<256, 256>>>(zf1, sf1, 32*2048, 2048, gany5, 8, ganyf1, 2475.f);

    // FC2: [256,2048] x [512,2048]^T + IF  (ppc=1, 128 groups)
    gemm_nt<<<dim3(8, 4), 256>>>(sf1, fc2w, zf2, 256, 512, 2048, ganyf1, 1, 128);
    if_kernel<<<64, 256>>>(zf2, sf2, 32*512, 512, ganyf1, 128, ganyf2, 1357.f);

    // FC3 + final IF + mean -> [32,10]
    fc3_if<<<2, 160>>>(sf2, fc3w, out, ganyf2, 388.f);
}